// round 2
// baseline (speedup 1.0000x reference)
#include <cuda_runtime.h>
#include <cuda_bf16.h>
#include <math.h>

// ---------------- problem constants ----------------
#define BATCH 32
#define IMG   56
#define CDIM  192
#define NHEAD 6
#define HDIM  32
#define WSZ   7
#define NTOK  49            // WSZ*WSZ
#define NWG   8             // windows per side
#define NWIN  64            // NWG*NWG
#define BWIN  (BATCH*NWIN)  // 2048
#define TOK   (BWIN*NTOK)   // 100352
#define MLPH  768

#define QKVSZ (BWIN*NHEAD*NTOK*HDIM)  // 19,267,584

// ---------------- scratch (static device globals; no allocation) -------------
__device__ float g_qkv[3u * (size_t)QKVSZ];          // q,k,v  [which][win][head][tok][d]
__device__ float g_attnout[(size_t)TOK * CDIM];      // attention output, window-token rows
__device__ float g_scratch[(size_t)TOK * CDIM];      // proj out / fc2 out
__device__ float g_x1[(size_t)BATCH * IMG * IMG * CDIM];
__device__ float g_hidden[(size_t)TOK * MLPH];
__device__ float g_tabsig[169 * NHEAD];              // 14*sigmoid(cpb) per (rel idx, head)
__device__ float g_scale[NHEAD];                     // exp(min(logit_scale, ln 100))

// ---------------- CPB table + scale kernel (tiny) ----------------
__global__ void tab_kernel(const float* __restrict__ w1, const float* __restrict__ b1,
                           const float* __restrict__ w2, const float* __restrict__ ls) {
    __shared__ float sW1[1024];
    __shared__ float sB1[512];
    __shared__ float sW2[NHEAD * 512];
    int tid = threadIdx.x;
    for (int i = tid; i < 1024; i += blockDim.x) sW1[i] = w1[i];
    for (int i = tid; i < 512;  i += blockDim.x) sB1[i] = b1[i];
    for (int i = tid; i < NHEAD * 512; i += blockDim.x) sW2[i] = w2[i];
    __syncthreads();

    if (tid < 169) {
        int i = tid / 13, j = tid % 13;
        float vh = (float)(i - 6) * (7.0f / 6.0f);
        float vw = (float)(j - 6) * (7.0f / 6.0f);
        const float inv_log2_7 = 0.35620719f;  // 1/log2(7)
        float th = copysignf(log2f(fabsf(vh) + 1.0f) * inv_log2_7, vh);
        float tw = copysignf(log2f(fabsf(vw) + 1.0f) * inv_log2_7, vw);
        float acc[NHEAD];
#pragma unroll
        for (int h = 0; h < NHEAD; h++) acc[h] = 0.f;
        for (int jj = 0; jj < 512; jj++) {
            float hval = fmaf(th, sW1[2 * jj], fmaf(tw, sW1[2 * jj + 1], sB1[jj]));
            hval = (hval > 0.f) ? hval : 0.01f * hval;   // leaky relu
#pragma unroll
            for (int h = 0; h < NHEAD; h++) acc[h] = fmaf(hval, sW2[h * 512 + jj], acc[h]);
        }
#pragma unroll
        for (int h = 0; h < NHEAD; h++)
            g_tabsig[tid * NHEAD + h] = 14.f / (1.f + expf(-acc[h]));
    }
    if (tid < NHEAD) {
        g_scale[tid] = expf(fminf(ls[tid], logf(100.f)));
    }
}

// ---------------- QKV GEMM with fused shift+window gather ----------------
// out[m][n] = sum_k xw[m][k]*qkv_w[n][k] + qkv_b[n], M=TOK, N=576, K=192
__global__ void __launch_bounds__(256) gemm_qkv_kernel(
        const float* __restrict__ x, const float* __restrict__ w,
        const float* __restrict__ bias) {
    __shared__ float As[16][64];
    __shared__ float Bs[16][64];
    const int K = CDIM;
    int tid = threadIdx.x;
    int m0 = blockIdx.y * 64, n0 = blockIdx.x * 64;
    int lr = tid >> 2;            // 0..63 : row within tile loaded by this thread
    int lk = (tid & 3) * 4;       // 0,4,8,12

    // gathered A row pointer (fixed per thread)
    int m = m0 + lr;
    int wv = m / NTOK, tk = m - wv * NTOK;
    int bb = wv >> 6, win = wv & 63;
    int r = tk / WSZ, c = tk - r * WSZ;
    int hp = (win >> 3) * WSZ + r + 3; if (hp >= IMG) hp -= IMG;
    int wp = (win & 7) * WSZ + c + 3;  if (wp >= IMG) wp -= IMG;
    const float* arow = x + ((size_t)((bb * IMG + hp) * IMG + wp)) * CDIM;
    const float* wrow = w + (size_t)(n0 + lr) * K;

    int tx = tid & 15, ty = tid >> 4;
    float acc[4][4] = {};
    for (int k0 = 0; k0 < K; k0 += 16) {
        float4 va = *(const float4*)(arow + k0 + lk);
        float4 vb = *(const float4*)(wrow + k0 + lk);
        __syncthreads();
        As[lk + 0][lr] = va.x; As[lk + 1][lr] = va.y; As[lk + 2][lr] = va.z; As[lk + 3][lr] = va.w;
        Bs[lk + 0][lr] = vb.x; Bs[lk + 1][lr] = vb.y; Bs[lk + 2][lr] = vb.z; Bs[lk + 3][lr] = vb.w;
        __syncthreads();
#pragma unroll
        for (int kk = 0; kk < 16; kk++) {
            float4 a = *(const float4*)&As[kk][ty * 4];
            float4 b = *(const float4*)&Bs[kk][tx * 4];
            float av[4] = {a.x, a.y, a.z, a.w};
            float bv[4] = {b.x, b.y, b.z, b.w};
#pragma unroll
            for (int i = 0; i < 4; i++)
#pragma unroll
                for (int j = 0; j < 4; j++) acc[i][j] = fmaf(av[i], bv[j], acc[i][j]);
        }
    }
    // epilogue: scatter into q/k/v head-major layout
#pragma unroll
    for (int i = 0; i < 4; i++) {
        int mm = m0 + ty * 4 + i;
        int wv2 = mm / NTOK, tk2 = mm - wv2 * NTOK;
#pragma unroll
        for (int j = 0; j < 4; j++) {
            int n = n0 + tx * 4 + j;
            float v = acc[i][j] + bias[n];
            int which = n / CDIM;
            int rem = n - which * CDIM;
            int head = rem >> 5, dd = rem & 31;
            g_qkv[(size_t)which * QKVSZ + ((size_t)(wv2 * NHEAD + head) * NTOK + tk2) * HDIM + dd] = v;
        }
    }
}

// ---------------- generic GEMM: out = A @ W^T + b ----------------
// ACT: 0 = none, 1 = exact GELU
template <int K, int ACT>
__global__ void __launch_bounds__(256) gemm_mn_kernel(
        const float* __restrict__ A, const float* __restrict__ Wg,
        const float* __restrict__ bias, float* __restrict__ out, int Ndim) {
    __shared__ float As[16][64];
    __shared__ float Bs[16][64];
    int tid = threadIdx.x;
    int m0 = blockIdx.y * 64, n0 = blockIdx.x * 64;
    int lr = tid >> 2;
    int lk = (tid & 3) * 4;
    const float* arow = A + (size_t)(m0 + lr) * K;
    const float* wrow = Wg + (size_t)(n0 + lr) * K;
    int tx = tid & 15, ty = tid >> 4;
    float acc[4][4] = {};
    for (int k0 = 0; k0 < K; k0 += 16) {
        float4 va = *(const float4*)(arow + k0 + lk);
        float4 vb = *(const float4*)(wrow + k0 + lk);
        __syncthreads();
        As[lk + 0][lr] = va.x; As[lk + 1][lr] = va.y; As[lk + 2][lr] = va.z; As[lk + 3][lr] = va.w;
        Bs[lk + 0][lr] = vb.x; Bs[lk + 1][lr] = vb.y; Bs[lk + 2][lr] = vb.z; Bs[lk + 3][lr] = vb.w;
        __syncthreads();
#pragma unroll
        for (int kk = 0; kk < 16; kk++) {
            float4 a = *(const float4*)&As[kk][ty * 4];
            float4 b = *(const float4*)&Bs[kk][tx * 4];
            float av[4] = {a.x, a.y, a.z, a.w};
            float bv[4] = {b.x, b.y, b.z, b.w};
#pragma unroll
            for (int i = 0; i < 4; i++)
#pragma unroll
                for (int j = 0; j < 4; j++) acc[i][j] = fmaf(av[i], bv[j], acc[i][j]);
        }
    }
#pragma unroll
    for (int i = 0; i < 4; i++) {
        size_t mm = m0 + ty * 4 + i;
#pragma unroll
        for (int j = 0; j < 4; j++) {
            int n = n0 + tx * 4 + j;
            float v = acc[i][j] + bias[n];
            if (ACT == 1) v = 0.5f * v * (1.0f + erff(v * 0.70710678118654752f));
            out[mm * Ndim + n] = v;
        }
    }
}

// ---------------- attention per (window, head) ----------------
__global__ void __launch_bounds__(128) attn_kernel() {
    int blk = blockIdx.x;
    int w = blk / NHEAD;
    int h = blk - w * NHEAD;
    int tid = threadIdx.x;

    __shared__ float sq[NTOK * HDIM];
    __shared__ float sk[NTOK * HDIM];
    __shared__ float sv[NTOK * HDIM];
    __shared__ float sP[NTOK * 50];
    __shared__ float stab[169];
    __shared__ int   sgid[NTOK];

    size_t base = ((size_t)(w * NHEAD + h) * NTOK) * HDIM;
    for (int i = tid; i < NTOK * HDIM; i += 128) {
        sq[i] = g_qkv[base + i];
        sk[i] = g_qkv[(size_t)QKVSZ + base + i];
        sv[i] = g_qkv[2 * (size_t)QKVSZ + base + i];
    }
    for (int i = tid; i < 169; i += 128) stab[i] = g_tabsig[i * NHEAD + h];

    int win = w & 63;
    int wi = win >> 3, wj = win & 7;
    if (tid < NTOK) {
        int r = tid / WSZ, c = tid - r * WSZ;
        int sh = wi * WSZ + r, sw = wj * WSZ + c;
        int gh = (sh < 49) ? 0 : ((sh < 53) ? 1 : 2);
        int gw = (sw < 49) ? 0 : ((sw < 53) ? 1 : 2);
        sgid[tid] = gh * 3 + gw;
    }
    __syncthreads();

    // normalize q (threads 0..48) and k (threads 64..112)
    if (tid < NTOK) {
        float s = 0.f;
#pragma unroll
        for (int d = 0; d < HDIM; d++) { float v = sq[tid * HDIM + d]; s += v * v; }
        float nrm = sqrtf(s);
        float inv = 1.0f / fmaxf(nrm, 1e-12f);
#pragma unroll
        for (int d = 0; d < HDIM; d++) sq[tid * HDIM + d] *= inv;
    } else if (tid >= 64 && tid < 64 + NTOK) {
        int rr = tid - 64;
        float s = 0.f;
#pragma unroll
        for (int d = 0; d < HDIM; d++) { float v = sk[rr * HDIM + d]; s += v * v; }
        float nrm = sqrtf(s);
        float inv = 1.0f / fmaxf(nrm, 1e-12f);
#pragma unroll
        for (int d = 0; d < HDIM; d++) sk[rr * HDIM + d] *= inv;
    }
    __syncthreads();

    float scale = g_scale[h];
    // logits
    for (int e = tid; e < NTOK * NTOK; e += 128) {
        int i = e / NTOK, j = e - i * NTOK;
        const float4* qa = (const float4*)&sq[i * HDIM];
        const float4* kb = (const float4*)&sk[j * HDIM];
        float s = 0.f;
#pragma unroll
        for (int t = 0; t < 8; t++) {
            float4 a = qa[t], b = kb[t];
            s += a.x * b.x + a.y * b.y + a.z * b.z + a.w * b.w;
        }
        int ri = i / WSZ, ci = i - ri * WSZ;
        int rj = j / WSZ, cj = j - rj * WSZ;
        int idx = (ri - rj + 6) * 13 + (ci - cj + 6);
        float mval = (sgid[i] != sgid[j]) ? -100.f : 0.f;
        sP[i * 50 + j] = s * scale + stab[idx] + mval;
    }
    __syncthreads();

    // softmax per row
    if (tid < NTOK) {
        float mx = -1e30f;
#pragma unroll
        for (int j = 0; j < NTOK; j++) mx = fmaxf(mx, sP[tid * 50 + j]);
        float sum = 0.f;
#pragma unroll
        for (int j = 0; j < NTOK; j++) {
            float e = __expf(sP[tid * 50 + j] - mx);
            sP[tid * 50 + j] = e;
            sum += e;
        }
        float inv = 1.0f / sum;
#pragma unroll
        for (int j = 0; j < NTOK; j++) sP[tid * 50 + j] *= inv;
    }
    __syncthreads();

    // O = P @ V ; write to [win][tok][head*32+d]
    for (int e = tid; e < NTOK * HDIM; e += 128) {
        int i = e >> 5, d = e & 31;
        float acc = 0.f;
#pragma unroll
        for (int j = 0; j < NTOK; j++) acc = fmaf(sP[i * 50 + j], sv[j * HDIM + d], acc);
        g_attnout[((size_t)(w * NTOK + i)) * CDIM + h * HDIM + d] = acc;
    }
}

// ---------------- LN + residual kernels ----------------
// ln1: x1[pos] = x[pos] + LN(proj_row)   (pos = window-reverse + unshift of row m)
__global__ void ln1_kernel(const float* __restrict__ src, const float* __restrict__ x,
                           const float* __restrict__ w, const float* __restrict__ b,
                           float* __restrict__ x1) {
    int m = blockIdx.x, t = threadIdx.x;
    float v = src[(size_t)m * CDIM + t];
    float s = v, s2 = v * v;
#pragma unroll
    for (int o = 16; o; o >>= 1) {
        s += __shfl_down_sync(0xffffffffu, s, o);
        s2 += __shfl_down_sync(0xffffffffu, s2, o);
    }
    __shared__ float rs[6], rs2[6];
    __shared__ float smean, srstd;
    if ((t & 31) == 0) { rs[t >> 5] = s; rs2[t >> 5] = s2; }
    __syncthreads();
    if (t == 0) {
        float a = 0.f, a2 = 0.f;
#pragma unroll
        for (int i = 0; i < 6; i++) { a += rs[i]; a2 += rs2[i]; }
        float mean = a / (float)CDIM;
        float var = a2 / (float)CDIM - mean * mean;
        smean = mean;
        srstd = rsqrtf(var + 1e-5f);
    }
    __syncthreads();
    float y = (v - smean) * srstd * w[t] + b[t];

    int wv = m / NTOK, tk = m - wv * NTOK;
    int bb = wv >> 6, win = wv & 63;
    int r = tk / WSZ, c = tk - r * WSZ;
    int hp = (win >> 3) * WSZ + r + 3; if (hp >= IMG) hp -= IMG;
    int wp = (win & 7) * WSZ + c + 3;  if (wp >= IMG) wp -= IMG;
    size_t idx = ((size_t)((bb * IMG + hp) * IMG + wp)) * CDIM + t;
    x1[idx] = x[idx] + y;
}

// ln2: out[m] = x1[m] + LN(fc2_row[m])   (identity row mapping)
__global__ void ln2_kernel(const float* __restrict__ src, const float* __restrict__ x1,
                           const float* __restrict__ w, const float* __restrict__ b,
                           float* __restrict__ out) {
    int m = blockIdx.x, t = threadIdx.x;
    float v = src[(size_t)m * CDIM + t];
    float s = v, s2 = v * v;
#pragma unroll
    for (int o = 16; o; o >>= 1) {
        s += __shfl_down_sync(0xffffffffu, s, o);
        s2 += __shfl_down_sync(0xffffffffu, s2, o);
    }
    __shared__ float rs[6], rs2[6];
    __shared__ float smean, srstd;
    if ((t & 31) == 0) { rs[t >> 5] = s; rs2[t >> 5] = s2; }
    __syncthreads();
    if (t == 0) {
        float a = 0.f, a2 = 0.f;
#pragma unroll
        for (int i = 0; i < 6; i++) { a += rs[i]; a2 += rs2[i]; }
        float mean = a / (float)CDIM;
        float var = a2 / (float)CDIM - mean * mean;
        smean = mean;
        srstd = rsqrtf(var + 1e-5f);
    }
    __syncthreads();
    float y = (v - smean) * srstd * w[t] + b[t];
    size_t idx = (size_t)m * CDIM + t;
    out[idx] = x1[idx] + y;
}

// ---------------- launcher ----------------
extern "C" void kernel_launch(void* const* d_in, const int* in_sizes, int n_in,
                              void* d_out, int out_size) {
    const float* x       = (const float*)d_in[0];
    const float* qkv_w   = (const float*)d_in[1];
    const float* qkv_b   = (const float*)d_in[2];
    const float* proj_w  = (const float*)d_in[3];
    const float* proj_b  = (const float*)d_in[4];
    const float* lscale  = (const float*)d_in[5];
    const float* cpb_w1  = (const float*)d_in[6];
    const float* cpb_b1  = (const float*)d_in[7];
    const float* cpb_w2  = (const float*)d_in[8];
    const float* n1w     = (const float*)d_in[9];
    const float* n1b     = (const float*)d_in[10];
    const float* n2w     = (const float*)d_in[11];
    const float* n2b     = (const float*)d_in[12];
    const float* fc1_w   = (const float*)d_in[13];
    const float* fc1_b   = (const float*)d_in[14];
    const float* fc2_w   = (const float*)d_in[15];
    const float* fc2_b   = (const float*)d_in[16];
    float* out = (float*)d_out;

    float *p_attn, *p_scr, *p_x1, *p_hid;
    cudaGetSymbolAddress((void**)&p_attn, g_attnout);
    cudaGetSymbolAddress((void**)&p_scr,  g_scratch);
    cudaGetSymbolAddress((void**)&p_x1,   g_x1);
    cudaGetSymbolAddress((void**)&p_hid,  g_hidden);

    const int MT = TOK / 64;  // 1568 M tiles

    tab_kernel<<<1, 256>>>(cpb_w1, cpb_b1, cpb_w2, lscale);
    gemm_qkv_kernel<<<dim3(576 / 64, MT), 256>>>(x, qkv_w, qkv_b);
    attn_kernel<<<BWIN * NHEAD, 128>>>();
    gemm_mn_kernel<CDIM, 0><<<dim3(CDIM / 64, MT), 256>>>(p_attn, proj_w, proj_b, p_scr, CDIM);
    ln1_kernel<<<TOK, CDIM>>>(p_scr, x, n1w, n1b, p_x1);
    gemm_mn_kernel<CDIM, 1><<<dim3(MLPH / 64, MT), 256>>>(p_x1, fc1_w, fc1_b, p_hid, MLPH);
    gemm_mn_kernel<MLPH, 0><<<dim3(CDIM / 64, MT), 256>>>(p_hid, fc2_w, fc2_b, p_scr, CDIM);
    ln2_kernel<<<TOK, CDIM>>>(p_scr, p_x1, n2w, n2b, out);
}

// round 3
// speedup vs baseline: 1.7072x; 1.7072x over previous
#include <cuda_runtime.h>
#include <cuda_bf16.h>
#include <math.h>

// ---------------- problem constants ----------------
#define BATCH 32
#define IMG   56
#define CDIM  192
#define NHEAD 6
#define HDIM  32
#define WSZ   7
#define NTOK  49
#define NWIN  64
#define BWIN  (BATCH*NWIN)  // 2048
#define TOK   (BWIN*NTOK)   // 100352
#define MLPH  768

#define QKVSZ (BWIN*NHEAD*NTOK*HDIM)

// ---------------- scratch ----------------
__device__ float g_qkv[3u * (size_t)QKVSZ];
__device__ float g_attnout[(size_t)TOK * CDIM];
__device__ float g_scratch[(size_t)TOK * CDIM];
__device__ float g_x1[(size_t)BATCH * IMG * IMG * CDIM];
__device__ float g_hidden[(size_t)TOK * MLPH];
__device__ float g_tabsig[169 * NHEAD];
__device__ float g_scale[NHEAD];

// ---------------- CPB table + scale (tiny) ----------------
__global__ void tab_kernel(const float* __restrict__ w1, const float* __restrict__ b1,
                           const float* __restrict__ w2, const float* __restrict__ ls) {
    __shared__ float sW1[1024];
    __shared__ float sB1[512];
    __shared__ float sW2[NHEAD * 512];
    int tid = threadIdx.x;
    for (int i = tid; i < 1024; i += blockDim.x) sW1[i] = w1[i];
    for (int i = tid; i < 512;  i += blockDim.x) sB1[i] = b1[i];
    for (int i = tid; i < NHEAD * 512; i += blockDim.x) sW2[i] = w2[i];
    __syncthreads();

    if (tid < 169) {
        int i = tid / 13, j = tid % 13;
        float vh = (float)(i - 6) * (7.0f / 6.0f);
        float vw = (float)(j - 6) * (7.0f / 6.0f);
        const float inv_log2_7 = 0.35620719f;
        float th = copysignf(log2f(fabsf(vh) + 1.0f) * inv_log2_7, vh);
        float tw = copysignf(log2f(fabsf(vw) + 1.0f) * inv_log2_7, vw);
        float acc[NHEAD];
#pragma unroll
        for (int h = 0; h < NHEAD; h++) acc[h] = 0.f;
        for (int jj = 0; jj < 512; jj++) {
            float hval = fmaf(th, sW1[2 * jj], fmaf(tw, sW1[2 * jj + 1], sB1[jj]));
            hval = (hval > 0.f) ? hval : 0.01f * hval;
#pragma unroll
            for (int h = 0; h < NHEAD; h++) acc[h] = fmaf(hval, sW2[h * 512 + jj], acc[h]);
        }
#pragma unroll
        for (int h = 0; h < NHEAD; h++)
            g_tabsig[tid * NHEAD + h] = 14.f / (1.f + expf(-acc[h]));
    }
    if (tid < NHEAD) g_scale[tid] = expf(fminf(ls[tid], logf(100.f)));
}

// ---------------- tf32 tensor-core GEMM ----------------
__device__ __forceinline__ unsigned f2tf(float f) {
    unsigned r; asm("cvt.rna.tf32.f32 %0, %1;" : "=r"(r) : "f"(f)); return r;
}
__device__ __forceinline__ void mma_tf32(float* c, const unsigned* a, const unsigned* b) {
    asm volatile("mma.sync.aligned.m16n8k8.row.col.f32.tf32.tf32.f32 "
        "{%0,%1,%2,%3}, {%4,%5,%6,%7}, {%8,%9}, {%0,%1,%2,%3};"
        : "+f"(c[0]), "+f"(c[1]), "+f"(c[2]), "+f"(c[3])
        : "r"(a[0]), "r"(a[1]), "r"(a[2]), "r"(a[3]), "r"(b[0]), "r"(b[1]));
}

#define ASTRIDE 20   // 16 k-slots + pad(4) -> conflict-free frag LDS

__device__ __forceinline__ const float* gather_row_ptr(const float* x, int m) {
    int wv = m / NTOK, tk = m - wv * NTOK;
    int bb = wv >> 6, win = wv & 63;
    int r = tk / WSZ, c = tk - r * WSZ;
    int hp = (win >> 3) * WSZ + r + 3; if (hp >= IMG) hp -= IMG;
    int wp = (win & 7) * WSZ + c + 3;  if (wp >= IMG) wp -= IMG;
    return x + ((size_t)((bb * IMG + hp) * IMG + wp)) * CDIM;
}

// GATHER: A rows come from x via swin shift+partition.
// SCATTER: epilogue writes into g_qkv head-major layout (out unused).
// ACT: 1 = exact GELU.
template <int GATHER, int ACT, int SCATTER>
__global__ void __launch_bounds__(256) tgemm_kernel(
        const float* __restrict__ A, const float* __restrict__ Wg,
        const float* __restrict__ bias, float* __restrict__ out,
        int K, int Ndim) {
    __shared__ unsigned As[128 * ASTRIDE];
    __shared__ unsigned Bs[64 * ASTRIDE];
    int tid = threadIdx.x;
    int m0 = blockIdx.y * 128, n0 = blockIdx.x * 64;
    int r0 = tid >> 2;            // 0..63
    int kc = (tid & 3) * 4;       // 0,4,8,12

    const float *arow0, *arow1;
    if (GATHER) {
        arow0 = gather_row_ptr(A, m0 + r0);
        arow1 = gather_row_ptr(A, m0 + r0 + 64);
    } else {
        arow0 = A + (size_t)(m0 + r0) * K;
        arow1 = A + (size_t)(m0 + r0 + 64) * K;
    }
    const float* brow = Wg + (size_t)(n0 + r0) * K;

    int lane = tid & 31, w = tid >> 5;
    int wm = w & 3, wn = w >> 2;          // warp grid 4(M) x 2(N)
    int g = lane >> 2, tg = lane & 3;

    float acc[2][4][4];
#pragma unroll
    for (int i = 0; i < 2; i++)
#pragma unroll
        for (int j = 0; j < 4; j++)
#pragma unroll
            for (int r = 0; r < 4; r++) acc[i][j][r] = 0.f;

    for (int k0 = 0; k0 < K; k0 += 16) {
        float4 va0 = *(const float4*)(arow0 + k0 + kc);
        float4 va1 = *(const float4*)(arow1 + k0 + kc);
        float4 vb  = *(const float4*)(brow  + k0 + kc);
        __syncthreads();
        *(uint4*)&As[r0 * ASTRIDE + kc] =
            make_uint4(f2tf(va0.x), f2tf(va0.y), f2tf(va0.z), f2tf(va0.w));
        *(uint4*)&As[(r0 + 64) * ASTRIDE + kc] =
            make_uint4(f2tf(va1.x), f2tf(va1.y), f2tf(va1.z), f2tf(va1.w));
        *(uint4*)&Bs[r0 * ASTRIDE + kc] =
            make_uint4(f2tf(vb.x), f2tf(vb.y), f2tf(vb.z), f2tf(vb.w));
        __syncthreads();

#pragma unroll
        for (int kk = 0; kk < 2; kk++) {
            int kb = kk * 8;
            unsigned afr[2][4], bfr[4][2];
#pragma unroll
            for (int i = 0; i < 2; i++) {
                int mrow = wm * 32 + i * 16 + g;
                afr[i][0] = As[mrow * ASTRIDE + kb + tg];
                afr[i][1] = As[(mrow + 8) * ASTRIDE + kb + tg];
                afr[i][2] = As[mrow * ASTRIDE + kb + tg + 4];
                afr[i][3] = As[(mrow + 8) * ASTRIDE + kb + tg + 4];
            }
#pragma unroll
            for (int j = 0; j < 4; j++) {
                int ncol = wn * 32 + j * 8 + g;
                bfr[j][0] = Bs[ncol * ASTRIDE + kb + tg];
                bfr[j][1] = Bs[ncol * ASTRIDE + kb + tg + 4];
            }
#pragma unroll
            for (int i = 0; i < 2; i++)
#pragma unroll
                for (int j = 0; j < 4; j++)
                    mma_tf32(acc[i][j], afr[i], bfr[j]);
        }
    }

    // epilogue
#pragma unroll
    for (int i = 0; i < 2; i++) {
        int rowb = m0 + wm * 32 + i * 16 + g;
#pragma unroll
        for (int j = 0; j < 4; j++) {
            int colb = n0 + wn * 32 + j * 8 + tg * 2;
#pragma unroll
            for (int r = 0; r < 4; r++) {
                int rr = rowb + (r >> 1) * 8;
                int cc = colb + (r & 1);
                float v = acc[i][j][r] + bias[cc];
                if (ACT == 1) v = 0.5f * v * (1.0f + erff(v * 0.70710678118654752f));
                if (SCATTER) {
                    int which = cc / CDIM;
                    int rem = cc - which * CDIM;
                    int head = rem >> 5, dd = rem & 31;
                    int wv = rr / NTOK, tk = rr - wv * NTOK;
                    g_qkv[(size_t)which * QKVSZ +
                          ((size_t)(wv * NHEAD + head) * NTOK + tk) * HDIM + dd] = v;
                } else {
                    out[(size_t)rr * Ndim + cc] = v;
                }
            }
        }
    }
}

// ---------------- attention per (window, head) ----------------
__global__ void __launch_bounds__(128) attn_kernel() {
    int blk = blockIdx.x;
    int w = blk / NHEAD;
    int h = blk - w * NHEAD;
    int tid = threadIdx.x;

    __shared__ float sq[NTOK * HDIM];
    __shared__ float sk[NTOK * HDIM];
    __shared__ float sv[NTOK * HDIM];
    __shared__ float sP[NTOK * 50];
    __shared__ float stab[169];
    __shared__ int   sgid[NTOK];

    size_t base = ((size_t)(w * NHEAD + h) * NTOK) * HDIM;
    for (int i = tid; i < NTOK * HDIM; i += 128) {
        sq[i] = g_qkv[base + i];
        sk[i] = g_qkv[(size_t)QKVSZ + base + i];
        sv[i] = g_qkv[2 * (size_t)QKVSZ + base + i];
    }
    for (int i = tid; i < 169; i += 128) stab[i] = g_tabsig[i * NHEAD + h];

    int win = w & 63;
    int wi = win >> 3, wj = win & 7;
    if (tid < NTOK) {
        int r = tid / WSZ, c = tid - r * WSZ;
        int sh = wi * WSZ + r, sw = wj * WSZ + c;
        int gh = (sh < 49) ? 0 : ((sh < 53) ? 1 : 2);
        int gw = (sw < 49) ? 0 : ((sw < 53) ? 1 : 2);
        sgid[tid] = gh * 3 + gw;
    }
    __syncthreads();

    if (tid < NTOK) {
        float s = 0.f;
#pragma unroll
        for (int d = 0; d < HDIM; d++) { float v = sq[tid * HDIM + d]; s += v * v; }
        float inv = 1.0f / fmaxf(sqrtf(s), 1e-12f);
#pragma unroll
        for (int d = 0; d < HDIM; d++) sq[tid * HDIM + d] *= inv;
    } else if (tid >= 64 && tid < 64 + NTOK) {
        int rr = tid - 64;
        float s = 0.f;
#pragma unroll
        for (int d = 0; d < HDIM; d++) { float v = sk[rr * HDIM + d]; s += v * v; }
        float inv = 1.0f / fmaxf(sqrtf(s), 1e-12f);
#pragma unroll
        for (int d = 0; d < HDIM; d++) sk[rr * HDIM + d] *= inv;
    }
    __syncthreads();

    float scale = g_scale[h];
    for (int e = tid; e < NTOK * NTOK; e += 128) {
        int i = e / NTOK, j = e - i * NTOK;
        const float4* qa = (const float4*)&sq[i * HDIM];
        const float4* kb = (const float4*)&sk[j * HDIM];
        float s = 0.f;
#pragma unroll
        for (int t = 0; t < 8; t++) {
            float4 a = qa[t], b = kb[t];
            s += a.x * b.x + a.y * b.y + a.z * b.z + a.w * b.w;
        }
        int ri = i / WSZ, ci = i - ri * WSZ;
        int rj = j / WSZ, cj = j - rj * WSZ;
        int idx = (ri - rj + 6) * 13 + (ci - cj + 6);
        float mval = (sgid[i] != sgid[j]) ? -100.f : 0.f;
        sP[i * 50 + j] = s * scale + stab[idx] + mval;
    }
    __syncthreads();

    if (tid < NTOK) {
        float mx = -1e30f;
#pragma unroll
        for (int j = 0; j < NTOK; j++) mx = fmaxf(mx, sP[tid * 50 + j]);
        float sum = 0.f;
#pragma unroll
        for (int j = 0; j < NTOK; j++) {
            float e = __expf(sP[tid * 50 + j] - mx);
            sP[tid * 50 + j] = e;
            sum += e;
        }
        float inv = 1.0f / sum;
#pragma unroll
        for (int j = 0; j < NTOK; j++) sP[tid * 50 + j] *= inv;
    }
    __syncthreads();

    for (int e = tid; e < NTOK * HDIM; e += 128) {
        int i = e >> 5, d = e & 31;
        float acc = 0.f;
#pragma unroll
        for (int j = 0; j < NTOK; j++) acc = fmaf(sP[i * 50 + j], sv[j * HDIM + d], acc);
        g_attnout[((size_t)(w * NTOK + i)) * CDIM + h * HDIM + d] = acc;
    }
}

// ---------------- LN + residual kernels ----------------
__global__ void ln1_kernel(const float* __restrict__ src, const float* __restrict__ x,
                           const float* __restrict__ w, const float* __restrict__ b,
                           float* __restrict__ x1) {
    int m = blockIdx.x, t = threadIdx.x;
    float v = src[(size_t)m * CDIM + t];
    float s = v, s2 = v * v;
#pragma unroll
    for (int o = 16; o; o >>= 1) {
        s += __shfl_down_sync(0xffffffffu, s, o);
        s2 += __shfl_down_sync(0xffffffffu, s2, o);
    }
    __shared__ float rs[6], rs2[6];
    __shared__ float smean, srstd;
    if ((t & 31) == 0) { rs[t >> 5] = s; rs2[t >> 5] = s2; }
    __syncthreads();
    if (t == 0) {
        float a = 0.f, a2 = 0.f;
#pragma unroll
        for (int i = 0; i < 6; i++) { a += rs[i]; a2 += rs2[i]; }
        float mean = a / (float)CDIM;
        float var = a2 / (float)CDIM - mean * mean;
        smean = mean; srstd = rsqrtf(var + 1e-5f);
    }
    __syncthreads();
    float y = (v - smean) * srstd * w[t] + b[t];

    int wv = m / NTOK, tk = m - wv * NTOK;
    int bb = wv >> 6, win = wv & 63;
    int r = tk / WSZ, c = tk - r * WSZ;
    int hp = (win >> 3) * WSZ + r + 3; if (hp >= IMG) hp -= IMG;
    int wp = (win & 7) * WSZ + c + 3;  if (wp >= IMG) wp -= IMG;
    size_t idx = ((size_t)((bb * IMG + hp) * IMG + wp)) * CDIM + t;
    x1[idx] = x[idx] + y;
}

__global__ void ln2_kernel(const float* __restrict__ src, const float* __restrict__ x1,
                           const float* __restrict__ w, const float* __restrict__ b,
                           float* __restrict__ out) {
    int m = blockIdx.x, t = threadIdx.x;
    float v = src[(size_t)m * CDIM + t];
    float s = v, s2 = v * v;
#pragma unroll
    for (int o = 16; o; o >>= 1) {
        s += __shfl_down_sync(0xffffffffu, s, o);
        s2 += __shfl_down_sync(0xffffffffu, s2, o);
    }
    __shared__ float rs[6], rs2[6];
    __shared__ float smean, srstd;
    if ((t & 31) == 0) { rs[t >> 5] = s; rs2[t >> 5] = s2; }
    __syncthreads();
    if (t == 0) {
        float a = 0.f, a2 = 0.f;
#pragma unroll
        for (int i = 0; i < 6; i++) { a += rs[i]; a2 += rs2[i]; }
        float mean = a / (float)CDIM;
        float var = a2 / (float)CDIM - mean * mean;
        smean = mean; srstd = rsqrtf(var + 1e-5f);
    }
    __syncthreads();
    float y = (v - smean) * srstd * w[t] + b[t];
    size_t idx = (size_t)m * CDIM + t;
    out[idx] = x1[idx] + y;
}

// ---------------- launcher ----------------
extern "C" void kernel_launch(void* const* d_in, const int* in_sizes, int n_in,
                              void* d_out, int out_size) {
    const float* x       = (const float*)d_in[0];
    const float* qkv_w   = (const float*)d_in[1];
    const float* qkv_b   = (const float*)d_in[2];
    const float* proj_w  = (const float*)d_in[3];
    const float* proj_b  = (const float*)d_in[4];
    const float* lscale  = (const float*)d_in[5];
    const float* cpb_w1  = (const float*)d_in[6];
    const float* cpb_b1  = (const float*)d_in[7];
    const float* cpb_w2  = (const float*)d_in[8];
    const float* n1w     = (const float*)d_in[9];
    const float* n1b     = (const float*)d_in[10];
    const float* n2w     = (const float*)d_in[11];
    const float* n2b     = (const float*)d_in[12];
    const float* fc1_w   = (const float*)d_in[13];
    const float* fc1_b   = (const float*)d_in[14];
    const float* fc2_w   = (const float*)d_in[15];
    const float* fc2_b   = (const float*)d_in[16];
    float* out = (float*)d_out;

    float *p_attn, *p_scr, *p_x1, *p_hid;
    cudaGetSymbolAddress((void**)&p_attn, g_attnout);
    cudaGetSymbolAddress((void**)&p_scr,  g_scratch);
    cudaGetSymbolAddress((void**)&p_x1,   g_x1);
    cudaGetSymbolAddress((void**)&p_hid,  g_hidden);

    const int MT = TOK / 128;  // 784 M tiles

    tab_kernel<<<1, 256>>>(cpb_w1, cpb_b1, cpb_w2, lscale);
    // QKV: gather A from x, scatter epilogue to g_qkv
    tgemm_kernel<1, 0, 1><<<dim3(576 / 64, MT), 256>>>(x, qkv_w, qkv_b, nullptr, CDIM, 576);
    attn_kernel<<<BWIN * NHEAD, 128>>>();
    // proj
    tgemm_kernel<0, 0, 0><<<dim3(CDIM / 64, MT), 256>>>(p_attn, proj_w, proj_b, p_scr, CDIM, CDIM);
    ln1_kernel<<<TOK, CDIM>>>(p_scr, x, n1w, n1b, p_x1);
    // fc1 + GELU
    tgemm_kernel<0, 1, 0><<<dim3(MLPH / 64, MT), 256>>>(p_x1, fc1_w, fc1_b, p_hid, CDIM, MLPH);
    // fc2
    tgemm_kernel<0, 0, 0><<<dim3(CDIM / 64, MT), 256>>>(p_hid, fc2_w, fc2_b, p_scr, MLPH, CDIM);
    ln2_kernel<<<TOK, CDIM>>>(p_scr, p_x1, n2w, n2b, out);
}

// round 5
// speedup vs baseline: 2.7848x; 1.6312x over previous
#include <cuda_runtime.h>
#include <cuda_bf16.h>
#include <math.h>

// ---------------- problem constants ----------------
#define BATCH 32
#define IMG   56
#define CDIM  192
#define NHEAD 6
#define HDIM  32
#define WSZ   7
#define NTOK  49
#define NWIN  64
#define BWIN  (BATCH*NWIN)  // 2048
#define TOK   (BWIN*NTOK)   // 100352
#define MLPH  768

#define QKVSZ (BWIN*NHEAD*NTOK*HDIM)

// ---------------- scratch ----------------
__device__ float g_qkv[3u * (size_t)QKVSZ];
__device__ float g_attnout[(size_t)TOK * CDIM];
__device__ float g_scratch[(size_t)TOK * CDIM];
__device__ float g_x1[(size_t)BATCH * IMG * IMG * CDIM];
__device__ float g_hidden[(size_t)TOK * MLPH];
__device__ float g_tabsig[169 * NHEAD];
__device__ float g_scale[NHEAD];

// ---------------- CPB table + scale (tiny) ----------------
__global__ void tab_kernel(const float* __restrict__ w1, const float* __restrict__ b1,
                           const float* __restrict__ w2, const float* __restrict__ ls) {
    __shared__ float sW1[1024];
    __shared__ float sB1[512];
    __shared__ float sW2[NHEAD * 512];
    int tid = threadIdx.x;
    for (int i = tid; i < 1024; i += blockDim.x) sW1[i] = w1[i];
    for (int i = tid; i < 512;  i += blockDim.x) sB1[i] = b1[i];
    for (int i = tid; i < NHEAD * 512; i += blockDim.x) sW2[i] = w2[i];
    __syncthreads();

    if (tid < 169) {
        int i = tid / 13, j = tid % 13;
        float vh = (float)(i - 6) * (7.0f / 6.0f);
        float vw = (float)(j - 6) * (7.0f / 6.0f);
        const float inv_log2_7 = 0.35620719f;
        float th = copysignf(log2f(fabsf(vh) + 1.0f) * inv_log2_7, vh);
        float tw = copysignf(log2f(fabsf(vw) + 1.0f) * inv_log2_7, vw);
        float acc[NHEAD];
#pragma unroll
        for (int h = 0; h < NHEAD; h++) acc[h] = 0.f;
        for (int jj = 0; jj < 512; jj++) {
            float hval = fmaf(th, sW1[2 * jj], fmaf(tw, sW1[2 * jj + 1], sB1[jj]));
            hval = (hval > 0.f) ? hval : 0.01f * hval;
#pragma unroll
            for (int h = 0; h < NHEAD; h++) acc[h] = fmaf(hval, sW2[h * 512 + jj], acc[h]);
        }
#pragma unroll
        for (int h = 0; h < NHEAD; h++)
            g_tabsig[tid * NHEAD + h] = 14.f / (1.f + expf(-acc[h]));
    }
    if (tid < NHEAD) g_scale[tid] = expf(fminf(ls[tid], logf(100.f)));
}

// ---------------- tf32 tensor-core GEMM ----------------
__device__ __forceinline__ unsigned f2tf(float f) {
    unsigned r; asm("cvt.rna.tf32.f32 %0, %1;" : "=r"(r) : "f"(f)); return r;
}
__device__ __forceinline__ void mma_tf32(float* c, const unsigned* a, const unsigned* b) {
    asm volatile("mma.sync.aligned.m16n8k8.row.col.f32.tf32.tf32.f32 "
        "{%0,%1,%2,%3}, {%4,%5,%6,%7}, {%8,%9}, {%0,%1,%2,%3};"
        : "+f"(c[0]), "+f"(c[1]), "+f"(c[2]), "+f"(c[3])
        : "r"(a[0]), "r"(a[1]), "r"(a[2]), "r"(a[3]), "r"(b[0]), "r"(b[1]));
}

#define ASTRIDE 20

__device__ __forceinline__ const float* gather_row_ptr(const float* x, int m) {
    int wv = m / NTOK, tk = m - wv * NTOK;
    int bb = wv >> 6, win = wv & 63;
    int r = tk / WSZ, c = tk - r * WSZ;
    int hp = (win >> 3) * WSZ + r + 3; if (hp >= IMG) hp -= IMG;
    int wp = (win & 7) * WSZ + c + 3;  if (wp >= IMG) wp -= IMG;
    return x + ((size_t)((bb * IMG + hp) * IMG + wp)) * CDIM;
}

// Block tile: 128(M) x 96(N), 6 warps (2x3) of 64x32 warp tiles, K-step 16.
template <int GATHER, int ACT, int SCATTER>
__global__ void __launch_bounds__(192, 2) tgemm_kernel(
        const float* __restrict__ A, const float* __restrict__ Wg,
        const float* __restrict__ bias, float* __restrict__ out,
        int K, int Ndim) {
    __shared__ unsigned As[128 * ASTRIDE];
    __shared__ unsigned Bs[96 * ASTRIDE];
    int tid = threadIdx.x;
    int m0 = blockIdx.y * 128, n0 = blockIdx.x * 96;

    // A load tasks: v = tid + s*192 (<512): row=v>>2, kc=(v&3)*4
    const float* arowp[3];
    int akc[3], aoff[3];
    bool aval2 = (tid < 128);
#pragma unroll
    for (int s = 0; s < 3; s++) {
        int v = tid + s * 192;
        int row = (v < 512) ? (v >> 2) : 0;
        akc[s] = (v & 3) * 4;
        aoff[s] = row * ASTRIDE + akc[s];
        arowp[s] = GATHER ? gather_row_ptr(A, m0 + row)
                          : (A + (size_t)(m0 + row) * K);
    }
    // B load tasks: v = tid + s*192 (<384): row=v>>2
    const float* browp[2];
    int bkc[2], boff[2];
#pragma unroll
    for (int s = 0; s < 2; s++) {
        int v = tid + s * 192;
        int row = v >> 2;
        bkc[s] = (v & 3) * 4;
        boff[s] = row * ASTRIDE + bkc[s];
        browp[s] = Wg + (size_t)(n0 + row) * K;
    }

    int lane = tid & 31, w = tid >> 5;
    int wm = w & 1, wn = w >> 1;          // 2(M) x 3(N)
    int g = lane >> 2, tg = lane & 3;

    float acc[4][4][4];
#pragma unroll
    for (int i = 0; i < 4; i++)
#pragma unroll
        for (int j = 0; j < 4; j++)
#pragma unroll
            for (int r = 0; r < 4; r++) acc[i][j][r] = 0.f;

    float4 pa[3], pb[2];
    pa[0] = *(const float4*)(arowp[0] + akc[0]);
    pa[1] = *(const float4*)(arowp[1] + akc[1]);
    if (aval2) pa[2] = *(const float4*)(arowp[2] + akc[2]);
    pb[0] = *(const float4*)(browp[0] + bkc[0]);
    pb[1] = *(const float4*)(browp[1] + bkc[1]);

    for (int k0 = 0; k0 < K; k0 += 16) {
        __syncthreads();
        *(uint4*)&As[aoff[0]] = make_uint4(f2tf(pa[0].x), f2tf(pa[0].y), f2tf(pa[0].z), f2tf(pa[0].w));
        *(uint4*)&As[aoff[1]] = make_uint4(f2tf(pa[1].x), f2tf(pa[1].y), f2tf(pa[1].z), f2tf(pa[1].w));
        if (aval2)
            *(uint4*)&As[aoff[2]] = make_uint4(f2tf(pa[2].x), f2tf(pa[2].y), f2tf(pa[2].z), f2tf(pa[2].w));
        *(uint4*)&Bs[boff[0]] = make_uint4(f2tf(pb[0].x), f2tf(pb[0].y), f2tf(pb[0].z), f2tf(pb[0].w));
        *(uint4*)&Bs[boff[1]] = make_uint4(f2tf(pb[1].x), f2tf(pb[1].y), f2tf(pb[1].z), f2tf(pb[1].w));
        __syncthreads();

        int kn = k0 + 16;
        if (kn < K) {
            pa[0] = *(const float4*)(arowp[0] + kn + akc[0]);
            pa[1] = *(const float4*)(arowp[1] + kn + akc[1]);
            if (aval2) pa[2] = *(const float4*)(arowp[2] + kn + akc[2]);
            pb[0] = *(const float4*)(browp[0] + kn + bkc[0]);
            pb[1] = *(const float4*)(browp[1] + kn + bkc[1]);
        }

#pragma unroll
        for (int kk = 0; kk < 16; kk += 8) {
            unsigned afr[4][4], bfr[4][2];
#pragma unroll
            for (int i = 0; i < 4; i++) {
                int mrow = wm * 64 + i * 16 + g;
                afr[i][0] = As[mrow * ASTRIDE + kk + tg];
                afr[i][1] = As[(mrow + 8) * ASTRIDE + kk + tg];
                afr[i][2] = As[mrow * ASTRIDE + kk + tg + 4];
                afr[i][3] = As[(mrow + 8) * ASTRIDE + kk + tg + 4];
            }
#pragma unroll
            for (int j = 0; j < 4; j++) {
                int ncol = wn * 32 + j * 8 + g;
                bfr[j][0] = Bs[ncol * ASTRIDE + kk + tg];
                bfr[j][1] = Bs[ncol * ASTRIDE + kk + tg + 4];
            }
#pragma unroll
            for (int i = 0; i < 4; i++)
#pragma unroll
                for (int j = 0; j < 4; j++)
                    mma_tf32(acc[i][j], afr[i], bfr[j]);
        }
    }

#pragma unroll
    for (int i = 0; i < 4; i++) {
        int rowb = m0 + wm * 64 + i * 16 + g;
#pragma unroll
        for (int j = 0; j < 4; j++) {
            int colb = n0 + wn * 32 + j * 8 + tg * 2;
#pragma unroll
            for (int r = 0; r < 4; r++) {
                int rr = rowb + (r >> 1) * 8;
                int cc = colb + (r & 1);
                float v = acc[i][j][r] + bias[cc];
                if (ACT == 1) v = 0.5f * v * (1.0f + erff(v * 0.70710678118654752f));
                if (SCATTER) {
                    int which = cc / CDIM;
                    int rem = cc - which * CDIM;
                    int head = rem >> 5, dd = rem & 31;
                    int wv = rr / NTOK, tk = rr - wv * NTOK;
                    g_qkv[(size_t)which * QKVSZ +
                          ((size_t)(wv * NHEAD + head) * NTOK + tk) * HDIM + dd] = v;
                } else {
                    out[(size_t)rr * Ndim + cc] = v;
                }
            }
        }
    }
}

// ---------------- attention per (window, head), 256 threads ----------------
__global__ void __launch_bounds__(256) attn_kernel() {
    int blk = blockIdx.x;
    int w = blk / NHEAD;
    int h = blk - w * NHEAD;
    int tid = threadIdx.x;
    int lane = tid & 31, wp = tid >> 5;

    __shared__ float sq[50 * 32];     // q rows (row 49 zero pad)
    __shared__ float skT[32 * 52];    // k transposed [d][j], cols 49..51 zero
    __shared__ float sv[49 * 32];
    __shared__ float sP[50 * 52];
    __shared__ float stab[169];
    __shared__ float qinv[50], kinv[49];
    __shared__ int   sgid[50];

    size_t base = ((size_t)(w * NHEAD + h) * NTOK) * HDIM;
    for (int i = tid; i < 1568; i += 256) {
        sq[i] = g_qkv[base + i];
        skT[(i & 31) * 52 + (i >> 5)] = g_qkv[(size_t)QKVSZ + base + i];
        sv[i] = g_qkv[2 * (size_t)QKVSZ + base + i];
    }
    if (tid < 32) {
        sq[1568 + tid] = 0.f;                       // pad q row 49
        skT[tid * 52 + 49] = 0.f;                   // pad k cols
        skT[tid * 52 + 50] = 0.f;
        skT[tid * 52 + 51] = 0.f;
    }
    for (int i = tid; i < 169; i += 256) stab[i] = g_tabsig[i * NHEAD + h];

    int win = w & 63;
    int wi = win >> 3, wj = win & 7;
    if (tid < 50) {
        int t = (tid < 49) ? tid : 48;
        int r = t / WSZ, c = t - r * WSZ;
        int sh = wi * WSZ + r, sw = wj * WSZ + c;
        int gh = (sh < 49) ? 0 : ((sh < 53) ? 1 : 2);
        int gw = (sw < 49) ? 0 : ((sw < 53) ? 1 : 2);
        sgid[tid] = gh * 3 + gw;
    }
    if (tid == 0) qinv[49] = 0.f;
    __syncthreads();

    // norms via warp-per-row (lane = d)
    for (int r = wp; r < 49; r += 8) {
        float vq = sq[r * 32 + lane];
        float vk = skT[lane * 52 + r];
        float sq2 = vq * vq, sk2 = vk * vk;
#pragma unroll
        for (int o = 16; o; o >>= 1) {
            sq2 += __shfl_xor_sync(0xffffffffu, sq2, o);
            sk2 += __shfl_xor_sync(0xffffffffu, sk2, o);
        }
        if (lane == 0) {
            qinv[r] = 1.0f / fmaxf(sqrtf(sq2), 1e-12f);
            kinv[r] = 1.0f / fmaxf(sqrtf(sk2), 1e-12f);
        }
    }
    __syncthreads();

    float scale = g_scale[h];
    // logits: tasks = 25 i-pairs x 13 j-quads
    for (int e = tid; e < 325; e += 256) {
        int ip = e / 13, jj = e - ip * 13;
        int i0 = 2 * ip, i1 = i0 + 1;
        int j0 = 4 * jj;
        float s0[4] = {0, 0, 0, 0}, s1[4] = {0, 0, 0, 0};
#pragma unroll
        for (int d = 0; d < 32; d++) {
            float q0 = sq[i0 * 32 + d], q1 = sq[i1 * 32 + d];
            float4 kv = *(const float4*)&skT[d * 52 + j0];
            s0[0] = fmaf(q0, kv.x, s0[0]); s0[1] = fmaf(q0, kv.y, s0[1]);
            s0[2] = fmaf(q0, kv.z, s0[2]); s0[3] = fmaf(q0, kv.w, s0[3]);
            s1[0] = fmaf(q1, kv.x, s1[0]); s1[1] = fmaf(q1, kv.y, s1[1]);
            s1[2] = fmaf(q1, kv.z, s1[2]); s1[3] = fmaf(q1, kv.w, s1[3]);
        }
        int ri0 = i0 / WSZ, ci0 = i0 - ri0 * WSZ;
        int ri1 = i1 / WSZ, ci1 = i1 - ri1 * WSZ;
        float qs0 = qinv[i0] * scale, qs1 = qinv[i1] * scale;
        int g0 = sgid[i0], g1 = sgid[i1];
#pragma unroll
        for (int q = 0; q < 4; q++) {
            int j = j0 + q;
            int jc = (j < 49) ? j : 48;
            int rj = jc / WSZ, cj = jc - rj * WSZ;
            float kz = kinv[jc];
            int gj = sgid[jc];
            int idx0 = (ri0 - rj + 6) * 13 + (ci0 - cj + 6);
            int idx1 = (ri1 - rj + 6) * 13 + (ci1 - cj + 6);
            idx1 = min(idx1, 168);
            float m0 = (g0 != gj) ? -100.f : 0.f;
            float m1 = (g1 != gj) ? -100.f : 0.f;
            sP[i0 * 52 + j] = s0[q] * qs0 * kz + stab[idx0] + m0;
            sP[i1 * 52 + j] = s1[q] * qs1 * kz + stab[idx1] + m1;
        }
    }
    __syncthreads();

    // softmax warp-per-row
    for (int r = wp; r < 49; r += 8) {
        float a = sP[r * 52 + lane];
        float b = (lane + 32 < 49) ? sP[r * 52 + lane + 32] : -1e30f;
        float mx = fmaxf(a, b);
#pragma unroll
        for (int o = 16; o; o >>= 1) mx = fmaxf(mx, __shfl_xor_sync(0xffffffffu, mx, o));
        float e0 = __expf(a - mx);
        float e1 = (lane + 32 < 49) ? __expf(b - mx) : 0.f;
        float sum = e0 + e1;
#pragma unroll
        for (int o = 16; o; o >>= 1) sum += __shfl_xor_sync(0xffffffffu, sum, o);
        float inv = 1.0f / sum;
        sP[r * 52 + lane] = e0 * inv;
        if (lane + 32 < 49) sP[r * 52 + lane + 32] = e1 * inv;
    }
    __syncthreads();

    // PV: tasks = 25 i-pairs x 8 d-quads
    for (int e = tid; e < 200; e += 256) {
        int ip = e >> 3, dd = e & 7;
        int i0 = 2 * ip, i1 = i0 + 1;
        int d0 = dd * 4;
        float a0x = 0, a0y = 0, a0z = 0, a0w = 0;
        float a1x = 0, a1y = 0, a1z = 0, a1w = 0;
#pragma unroll
        for (int j = 0; j < 49; j++) {
            float p0 = sP[i0 * 52 + j], p1 = sP[i1 * 52 + j];
            float4 vv = *(const float4*)&sv[j * 32 + d0];
            a0x = fmaf(p0, vv.x, a0x); a0y = fmaf(p0, vv.y, a0y);
            a0z = fmaf(p0, vv.z, a0z); a0w = fmaf(p0, vv.w, a0w);
            a1x = fmaf(p1, vv.x, a1x); a1y = fmaf(p1, vv.y, a1y);
            a1z = fmaf(p1, vv.z, a1z); a1w = fmaf(p1, vv.w, a1w);
        }
        size_t ob = ((size_t)(w * NTOK + i0)) * CDIM + h * HDIM + d0;
        *(float4*)&g_attnout[ob] = make_float4(a0x, a0y, a0z, a0w);
        if (i1 < 49) {
            size_t ob1 = ((size_t)(w * NTOK + i1)) * CDIM + h * HDIM + d0;
            *(float4*)&g_attnout[ob1] = make_float4(a1x, a1y, a1z, a1w);
        }
    }
}

// ---------------- LN + residual: warp-per-row ----------------
__global__ void __launch_bounds__(256) ln1_kernel(
        const float* __restrict__ src, const float* __restrict__ x,
        const float* __restrict__ w, const float* __restrict__ b,
        float* __restrict__ x1) {
    int row = blockIdx.x * 8 + (threadIdx.x >> 5);
    int lane = threadIdx.x & 31;
    const float* s = src + (size_t)row * CDIM;
    float v[6];
    float sum = 0.f, sq = 0.f;
#pragma unroll
    for (int c = 0; c < 6; c++) {
        v[c] = s[lane + c * 32];
        sum += v[c]; sq = fmaf(v[c], v[c], sq);
    }
#pragma unroll
    for (int o = 16; o; o >>= 1) {
        sum += __shfl_xor_sync(0xffffffffu, sum, o);
        sq  += __shfl_xor_sync(0xffffffffu, sq, o);
    }
    float mean = sum * (1.0f / CDIM);
    float rstd = rsqrtf(sq * (1.0f / CDIM) - mean * mean + 1e-5f);

    int wv = row / NTOK, tk = row - wv * NTOK;
    int bb = wv >> 6, win = wv & 63;
    int r = tk / WSZ, c = tk - r * WSZ;
    int hp = (win >> 3) * WSZ + r + 3; if (hp >= IMG) hp -= IMG;
    int wpc = (win & 7) * WSZ + c + 3; if (wpc >= IMG) wpc -= IMG;
    size_t idx = ((size_t)((bb * IMG + hp) * IMG + wpc)) * CDIM;
#pragma unroll
    for (int cc = 0; cc < 6; cc++) {
        int t = lane + cc * 32;
        float y = (v[cc] - mean) * rstd * w[t] + b[t];
        x1[idx + t] = x[idx + t] + y;
    }
}

__global__ void __launch_bounds__(256) ln2_kernel(
        const float* __restrict__ src, const float* __restrict__ x1,
        const float* __restrict__ w, const float* __restrict__ b,
        float* __restrict__ out) {
    int row = blockIdx.x * 8 + (threadIdx.x >> 5);
    int lane = threadIdx.x & 31;
    const float* s = src + (size_t)row * CDIM;
    float v[6];
    float sum = 0.f, sq = 0.f;
#pragma unroll
    for (int c = 0; c < 6; c++) {
        v[c] = s[lane + c * 32];
        sum += v[c]; sq = fmaf(v[c], v[c], sq);
    }
#pragma unroll
    for (int o = 16; o; o >>= 1) {
        sum += __shfl_xor_sync(0xffffffffu, sum, o);
        sq  += __shfl_xor_sync(0xffffffffu, sq, o);
    }
    float mean = sum * (1.0f / CDIM);
    float rstd = rsqrtf(sq * (1.0f / CDIM) - mean * mean + 1e-5f);
    size_t idx = (size_t)row * CDIM;
#pragma unroll
    for (int cc = 0; cc < 6; cc++) {
        int t = lane + cc * 32;
        float y = (v[cc] - mean) * rstd * w[t] + b[t];
        out[idx + t] = x1[idx + t] + y;
    }
}

// ---------------- launcher ----------------
extern "C" void kernel_launch(void* const* d_in, const int* in_sizes, int n_in,
                              void* d_out, int out_size) {
    const float* x       = (const float*)d_in[0];
    const float* qkv_w   = (const float*)d_in[1];
    const float* qkv_b   = (const float*)d_in[2];
    const float* proj_w  = (const float*)d_in[3];
    const float* proj_b  = (const float*)d_in[4];
    const float* lscale  = (const float*)d_in[5];
    const float* cpb_w1  = (const float*)d_in[6];
    const float* cpb_b1  = (const float*)d_in[7];
    const float* cpb_w2  = (const float*)d_in[8];
    const float* n1w     = (const float*)d_in[9];
    const float* n1b     = (const float*)d_in[10];
    const float* n2w     = (const float*)d_in[11];
    const float* n2b     = (const float*)d_in[12];
    const float* fc1_w   = (const float*)d_in[13];
    const float* fc1_b   = (const float*)d_in[14];
    const float* fc2_w   = (const float*)d_in[15];
    const float* fc2_b   = (const float*)d_in[16];
    float* out = (float*)d_out;

    float *p_attn, *p_scr, *p_x1, *p_hid;
    cudaGetSymbolAddress((void**)&p_attn, g_attnout);
    cudaGetSymbolAddress((void**)&p_scr,  g_scratch);
    cudaGetSymbolAddress((void**)&p_x1,   g_x1);
    cudaGetSymbolAddress((void**)&p_hid,  g_hidden);

    const int MT = TOK / 128;  // 784

    tab_kernel<<<1, 256>>>(cpb_w1, cpb_b1, cpb_w2, lscale);
    // QKV: N=576 -> 6 tiles of 96
    tgemm_kernel<1, 0, 1><<<dim3(6, MT), 192>>>(x, qkv_w, qkv_b, nullptr, CDIM, 576);
    attn_kernel<<<BWIN * NHEAD, 256>>>();
    // proj: N=192 -> 2 tiles
    tgemm_kernel<0, 0, 0><<<dim3(2, MT), 192>>>(p_attn, proj_w, proj_b, p_scr, CDIM, CDIM);
    ln1_kernel<<<TOK / 8, 256>>>(p_scr, x, n1w, n1b, p_x1);
    // fc1 + GELU: N=768 -> 8 tiles
    tgemm_kernel<0, 1, 0><<<dim3(8, MT), 192>>>(p_x1, fc1_w, fc1_b, p_hid, CDIM, MLPH);
    // fc2: N=192, K=768
    tgemm_kernel<0, 0, 0><<<dim3(2, MT), 192>>>(p_hid, fc2_w, fc2_b, p_scr, MLPH, CDIM);
    ln2_kernel<<<TOK / 8, 256>>>(p_scr, p_x1, n2w, n2b, out);
}

// round 10
// speedup vs baseline: 3.0049x; 1.0790x over previous
#include <cuda_runtime.h>
#include <cuda_bf16.h>
#include <math.h>

// ---------------- problem constants ----------------
#define BATCH 32
#define IMG   56
#define CDIM  192
#define NHEAD 6
#define HDIM  32
#define WSZ   7
#define NTOK  49
#define NWIN  64
#define BWIN  (BATCH*NWIN)  // 2048
#define TOK   (BWIN*NTOK)   // 100352
#define MLPH  768

#define QKVSZ (BWIN*NHEAD*NTOK*HDIM)

// ---------------- scratch ----------------
__device__ float g_qkv[3u * (size_t)QKVSZ];
__device__ float g_attnout[(size_t)TOK * CDIM];
__device__ float g_scratch[(size_t)TOK * CDIM];
__device__ float g_x1[(size_t)BATCH * IMG * IMG * CDIM];
__device__ float g_hidden[(size_t)TOK * MLPH];
__device__ float g_tabsig[169 * NHEAD];
__device__ float g_scale[NHEAD];

// ---------------- CPB table + scale (tiny) ----------------
__global__ void tab_kernel(const float* __restrict__ w1, const float* __restrict__ b1,
                           const float* __restrict__ w2, const float* __restrict__ ls) {
    __shared__ float sW1[1024];
    __shared__ float sB1[512];
    __shared__ float sW2[NHEAD * 512];
    int tid = threadIdx.x;
    for (int i = tid; i < 1024; i += blockDim.x) sW1[i] = w1[i];
    for (int i = tid; i < 512;  i += blockDim.x) sB1[i] = b1[i];
    for (int i = tid; i < NHEAD * 512; i += blockDim.x) sW2[i] = w2[i];
    __syncthreads();

    if (tid < 169) {
        int i = tid / 13, j = tid % 13;
        float vh = (float)(i - 6) * (7.0f / 6.0f);
        float vw = (float)(j - 6) * (7.0f / 6.0f);
        const float inv_log2_7 = 0.35620719f;
        float th = copysignf(log2f(fabsf(vh) + 1.0f) * inv_log2_7, vh);
        float tw = copysignf(log2f(fabsf(vw) + 1.0f) * inv_log2_7, vw);
        float acc[NHEAD];
#pragma unroll
        for (int h = 0; h < NHEAD; h++) acc[h] = 0.f;
        for (int jj = 0; jj < 512; jj++) {
            float hval = fmaf(th, sW1[2 * jj], fmaf(tw, sW1[2 * jj + 1], sB1[jj]));
            hval = (hval > 0.f) ? hval : 0.01f * hval;
#pragma unroll
            for (int h = 0; h < NHEAD; h++) acc[h] = fmaf(hval, sW2[h * 512 + jj], acc[h]);
        }
#pragma unroll
        for (int h = 0; h < NHEAD; h++)
            g_tabsig[tid * NHEAD + h] = 14.f / (1.f + expf(-acc[h]));
    }
    if (tid < NHEAD) g_scale[tid] = expf(fminf(ls[tid], logf(100.f)));
}

// ---------------- tf32 helpers ----------------
__device__ __forceinline__ unsigned f2tf(float f) {
    unsigned r; asm("cvt.rna.tf32.f32 %0, %1;" : "=r"(r) : "f"(f)); return r;
}
__device__ __forceinline__ float f2tff(float f) {
    return __uint_as_float(f2tf(f));
}
__device__ __forceinline__ void mma_tf32(float* c, const unsigned* a, const unsigned* b) {
    asm volatile("mma.sync.aligned.m16n8k8.row.col.f32.tf32.tf32.f32 "
        "{%0,%1,%2,%3}, {%4,%5,%6,%7}, {%8,%9}, {%0,%1,%2,%3};"
        : "+f"(c[0]), "+f"(c[1]), "+f"(c[2]), "+f"(c[3])
        : "r"(a[0]), "r"(a[1]), "r"(a[2]), "r"(a[3]), "r"(b[0]), "r"(b[1]));
}

#define ASTRIDE 20

__device__ __forceinline__ const float* gather_row_ptr(const float* x, int m) {
    int wv = m / NTOK, tk = m - wv * NTOK;
    int bb = wv >> 6, win = wv & 63;
    int r = tk / WSZ, c = tk - r * WSZ;
    int hp = (win >> 3) * WSZ + r + 3; if (hp >= IMG) hp -= IMG;
    int wp = (win & 7) * WSZ + c + 3;  if (wp >= IMG) wp -= IMG;
    return x + ((size_t)((bb * IMG + hp) * IMG + wp)) * CDIM;
}

// ---------------- tf32 GEMM (unchanged from R5) ----------------
template <int GATHER, int ACT, int SCATTER>
__global__ void __launch_bounds__(192, 2) tgemm_kernel(
        const float* __restrict__ A, const float* __restrict__ Wg,
        const float* __restrict__ bias, float* __restrict__ out,
        int K, int Ndim) {
    __shared__ unsigned As[128 * ASTRIDE];
    __shared__ unsigned Bs[96 * ASTRIDE];
    int tid = threadIdx.x;
    int m0 = blockIdx.y * 128, n0 = blockIdx.x * 96;

    const float* arowp[3];
    int akc[3], aoff[3];
    bool aval2 = (tid < 128);
#pragma unroll
    for (int s = 0; s < 3; s++) {
        int v = tid + s * 192;
        int row = (v < 512) ? (v >> 2) : 0;
        akc[s] = (v & 3) * 4;
        aoff[s] = row * ASTRIDE + akc[s];
        arowp[s] = GATHER ? gather_row_ptr(A, m0 + row)
                          : (A + (size_t)(m0 + row) * K);
    }
    const float* browp[2];
    int bkc[2], boff[2];
#pragma unroll
    for (int s = 0; s < 2; s++) {
        int v = tid + s * 192;
        int row = v >> 2;
        bkc[s] = (v & 3) * 4;
        boff[s] = row * ASTRIDE + bkc[s];
        browp[s] = Wg + (size_t)(n0 + row) * K;
    }

    int lane = tid & 31, w = tid >> 5;
    int wm = w & 1, wn = w >> 1;
    int g = lane >> 2, tg = lane & 3;

    float acc[4][4][4];
#pragma unroll
    for (int i = 0; i < 4; i++)
#pragma unroll
        for (int j = 0; j < 4; j++)
#pragma unroll
            for (int r = 0; r < 4; r++) acc[i][j][r] = 0.f;

    float4 pa[3], pb[2];
    pa[0] = *(const float4*)(arowp[0] + akc[0]);
    pa[1] = *(const float4*)(arowp[1] + akc[1]);
    if (aval2) pa[2] = *(const float4*)(arowp[2] + akc[2]);
    pb[0] = *(const float4*)(browp[0] + bkc[0]);
    pb[1] = *(const float4*)(browp[1] + bkc[1]);

    for (int k0 = 0; k0 < K; k0 += 16) {
        __syncthreads();
        *(uint4*)&As[aoff[0]] = make_uint4(f2tf(pa[0].x), f2tf(pa[0].y), f2tf(pa[0].z), f2tf(pa[0].w));
        *(uint4*)&As[aoff[1]] = make_uint4(f2tf(pa[1].x), f2tf(pa[1].y), f2tf(pa[1].z), f2tf(pa[1].w));
        if (aval2)
            *(uint4*)&As[aoff[2]] = make_uint4(f2tf(pa[2].x), f2tf(pa[2].y), f2tf(pa[2].z), f2tf(pa[2].w));
        *(uint4*)&Bs[boff[0]] = make_uint4(f2tf(pb[0].x), f2tf(pb[0].y), f2tf(pb[0].z), f2tf(pb[0].w));
        *(uint4*)&Bs[boff[1]] = make_uint4(f2tf(pb[1].x), f2tf(pb[1].y), f2tf(pb[1].z), f2tf(pb[1].w));
        __syncthreads();

        int kn = k0 + 16;
        if (kn < K) {
            pa[0] = *(const float4*)(arowp[0] + kn + akc[0]);
            pa[1] = *(const float4*)(arowp[1] + kn + akc[1]);
            if (aval2) pa[2] = *(const float4*)(arowp[2] + kn + akc[2]);
            pb[0] = *(const float4*)(browp[0] + kn + bkc[0]);
            pb[1] = *(const float4*)(browp[1] + kn + bkc[1]);
        }

#pragma unroll
        for (int kk = 0; kk < 16; kk += 8) {
            unsigned afr[4][4], bfr[4][2];
#pragma unroll
            for (int i = 0; i < 4; i++) {
                int mrow = wm * 64 + i * 16 + g;
                afr[i][0] = As[mrow * ASTRIDE + kk + tg];
                afr[i][1] = As[(mrow + 8) * ASTRIDE + kk + tg];
                afr[i][2] = As[mrow * ASTRIDE + kk + tg + 4];
                afr[i][3] = As[(mrow + 8) * ASTRIDE + kk + tg + 4];
            }
#pragma unroll
            for (int j = 0; j < 4; j++) {
                int ncol = wn * 32 + j * 8 + g;
                bfr[j][0] = Bs[ncol * ASTRIDE + kk + tg];
                bfr[j][1] = Bs[ncol * ASTRIDE + kk + tg + 4];
            }
#pragma unroll
            for (int i = 0; i < 4; i++)
#pragma unroll
                for (int j = 0; j < 4; j++)
                    mma_tf32(acc[i][j], afr[i], bfr[j]);
        }
    }

#pragma unroll
    for (int i = 0; i < 4; i++) {
        int rowb = m0 + wm * 64 + i * 16 + g;
#pragma unroll
        for (int j = 0; j < 4; j++) {
            int colb = n0 + wn * 32 + j * 8 + tg * 2;
#pragma unroll
            for (int r = 0; r < 4; r++) {
                int rr = rowb + (r >> 1) * 8;
                int cc = colb + (r & 1);
                float v = acc[i][j][r] + bias[cc];
                if (ACT == 1) v = 0.5f * v * (1.0f + erff(v * 0.70710678118654752f));
                if (SCATTER) {
                    int which = cc / CDIM;
                    int rem = cc - which * CDIM;
                    int head = rem >> 5, dd = rem & 31;
                    int wv = rr / NTOK, tk = rr - wv * NTOK;
                    g_qkv[(size_t)which * QKVSZ +
                          ((size_t)(wv * NHEAD + head) * NTOK + tk) * HDIM + dd] = v;
                } else {
                    out[(size_t)rr * Ndim + cc] = v;
                }
            }
        }
    }
}

// ---------------- tensor-core attention ----------------
// 1 block = 1 (window, head). 128 threads = 4 warps; warp wr owns S rows
// [wr*16, wr*16+16). QK^T via 3xtf32 split (fp32-grade logits), PV single tf32.
// smem float offsets:
#define OQH 0
#define OQL 2304
#define OKH 4608
#define OKL 6912
#define OVT 9216               // 32 x 68 (V transposed, tf32)
#define OP  11392              // 64 x 68 (P, tf32)
#define OQI 15744
#define OKI 15808
#define OTAB 15872             // 176
#define OGID 16048             // 64
#define ATT_SMEM_FLOATS 16112
#define ATT_SMEM_BYTES (ATT_SMEM_FLOATS * 4)

__global__ void __launch_bounds__(128) attn_kernel() {
    extern __shared__ float smx[];
    float* sQh = smx + OQH;    // stride 36
    float* sQl = smx + OQL;
    float* sKh = smx + OKH;
    float* sKl = smx + OKL;
    float* sVT = smx + OVT;    // stride 68, [d][j]
    float* sP  = smx + OP;     // stride 68
    float* qinv = smx + OQI;
    float* kinv = smx + OKI;
    float* stab = smx + OTAB;
    int*   sgid = (int*)(smx + OGID);

    int blk = blockIdx.x;
    int w = blk / NHEAD;
    int h = blk - w * NHEAD;
    int tid = threadIdx.x;
    int lane = tid & 31, wr = tid >> 5;
    int g = lane >> 2, tg = lane & 3;

    size_t base = ((size_t)(w * NHEAD + h) * NTOK) * HDIM;
    const float* qp = g_qkv + base;
    const float* kp = g_qkv + (size_t)QKVSZ + base;
    const float* vp = g_qkv + 2 * (size_t)QKVSZ + base;

    // zero pad rows 49..63 of Q/K (cols 0..31) and cols 48..63 of VT
    for (int i = tid; i < 15 * 32; i += 128) {
        int r = 49 + (i >> 5), c = i & 31;
        sQh[r * 36 + c] = 0.f; sQl[r * 36 + c] = 0.f;
        sKh[r * 36 + c] = 0.f; sKl[r * 36 + c] = 0.f;
    }
    for (int i = tid; i < 32 * 16; i += 128) {
        int d = i >> 4, j = 48 + (i & 15);
        sVT[d * 68 + j] = 0.f;
    }

    // load + split/convert
    for (int idx = tid; idx < 392; idx += 128) {    // 49 rows x 8 float4
        int r = idx >> 3, c4 = (idx & 7) * 4;
        float4 q = *(const float4*)(qp + r * 32 + c4);
        float4 k = *(const float4*)(kp + r * 32 + c4);
        float4 v = *(const float4*)(vp + r * 32 + c4);
        float qh0 = f2tff(q.x), qh1 = f2tff(q.y), qh2 = f2tff(q.z), qh3 = f2tff(q.w);
        sQh[r * 36 + c4 + 0] = qh0; sQl[r * 36 + c4 + 0] = f2tff(q.x - qh0);
        sQh[r * 36 + c4 + 1] = qh1; sQl[r * 36 + c4 + 1] = f2tff(q.y - qh1);
        sQh[r * 36 + c4 + 2] = qh2; sQl[r * 36 + c4 + 2] = f2tff(q.z - qh2);
        sQh[r * 36 + c4 + 3] = qh3; sQl[r * 36 + c4 + 3] = f2tff(q.w - qh3);
        float kh0 = f2tff(k.x), kh1 = f2tff(k.y), kh2 = f2tff(k.z), kh3 = f2tff(k.w);
        sKh[r * 36 + c4 + 0] = kh0; sKl[r * 36 + c4 + 0] = f2tff(k.x - kh0);
        sKh[r * 36 + c4 + 1] = kh1; sKl[r * 36 + c4 + 1] = f2tff(k.y - kh1);
        sKh[r * 36 + c4 + 2] = kh2; sKl[r * 36 + c4 + 2] = f2tff(k.z - kh2);
        sKh[r * 36 + c4 + 3] = kh3; sKl[r * 36 + c4 + 3] = f2tff(k.w - kh3);
        sVT[(c4 + 0) * 68 + r] = f2tff(v.x);
        sVT[(c4 + 1) * 68 + r] = f2tff(v.y);
        sVT[(c4 + 2) * 68 + r] = f2tff(v.z);
        sVT[(c4 + 3) * 68 + r] = f2tff(v.w);
    }
    for (int i = tid; i < 169; i += 128) stab[i] = g_tabsig[i * NHEAD + h];

    int win = w & 63;
    int wi = win >> 3, wj = win & 7;
    if (tid < 64) {
        int t = (tid < 49) ? tid : 48;
        int r = t / WSZ, c = t - r * WSZ;
        int sh = wi * WSZ + r, sw = wj * WSZ + c;
        int gh = (sh < 49) ? 0 : ((sh < 53) ? 1 : 2);
        int gw = (sw < 49) ? 0 : ((sw < 53) ? 1 : 2);
        sgid[tid] = gh * 3 + gw;
    }
    __syncthreads();

    // norms from reconstructed hi+lo (== fp32 to ~2^-24)
    if (tid < 49) {
        float s = 0.f;
#pragma unroll
        for (int d = 0; d < 32; d++) {
            float v = sQh[tid * 36 + d] + sQl[tid * 36 + d];
            s = fmaf(v, v, s);
        }
        qinv[tid] = 1.0f / fmaxf(sqrtf(s), 1e-12f);
    } else if (tid >= 64 && tid < 64 + 49) {
        int r = tid - 64;
        float s = 0.f;
#pragma unroll
        for (int d = 0; d < 32; d++) {
            float v = sKh[r * 36 + d] + sKl[r * 36 + d];
            s = fmaf(v, v, s);
        }
        kinv[r] = 1.0f / fmaxf(sqrtf(s), 1e-12f);
    }
    __syncthreads();

    // ---- QK^T : S tile rows [wr*16, wr*16+16), cols 0..63, 3xtf32 ----
    float acc[8][4];
#pragma unroll
    for (int n = 0; n < 8; n++)
#pragma unroll
        for (int r = 0; r < 4; r++) acc[n][r] = 0.f;

    int arow = wr * 16 + g;
#pragma unroll
    for (int kk = 0; kk < 4; kk++) {
        int kb = kk * 8;
        unsigned ah[4], al[4];
        ah[0] = __float_as_uint(sQh[arow * 36 + kb + tg]);
        ah[1] = __float_as_uint(sQh[(arow + 8) * 36 + kb + tg]);
        ah[2] = __float_as_uint(sQh[arow * 36 + kb + tg + 4]);
        ah[3] = __float_as_uint(sQh[(arow + 8) * 36 + kb + tg + 4]);
        al[0] = __float_as_uint(sQl[arow * 36 + kb + tg]);
        al[1] = __float_as_uint(sQl[(arow + 8) * 36 + kb + tg]);
        al[2] = __float_as_uint(sQl[arow * 36 + kb + tg + 4]);
        al[3] = __float_as_uint(sQl[(arow + 8) * 36 + kb + tg + 4]);
#pragma unroll
        for (int n = 0; n < 8; n++) {
            int bj = n * 8 + g;
            unsigned bh[2], bl[2];
            bh[0] = __float_as_uint(sKh[bj * 36 + kb + tg]);
            bh[1] = __float_as_uint(sKh[bj * 36 + kb + tg + 4]);
            bl[0] = __float_as_uint(sKl[bj * 36 + kb + tg]);
            bl[1] = __float_as_uint(sKl[bj * 36 + kb + tg + 4]);
            mma_tf32(acc[n], al, bh);
            mma_tf32(acc[n], ah, bl);
            mma_tf32(acc[n], ah, bh);
        }
    }

    // ---- bias/mask epilogue + softmax (rows iA = wr*16+g, iB = iA+8) ----
    float scale = g_scale[h];
    int iA = wr * 16 + g, iB = iA + 8;
    bool vA = (iA < 49), vB = (iB < 49);
    int riA = 0, ciA = 0, giA = 0, riB = 0, ciB = 0, giB = 0;
    float qsA = 0.f, qsB = 0.f;
    if (vA) { riA = iA / WSZ; ciA = iA - riA * WSZ; giA = sgid[iA]; qsA = qinv[iA] * scale; }
    if (vB) { riB = iB / WSZ; ciB = iB - riB * WSZ; giB = sgid[iB]; qsB = qinv[iB] * scale; }

#pragma unroll
    for (int n = 0; n < 8; n++) {
#pragma unroll
        for (int r = 0; r < 4; r++) {
            int j = n * 8 + tg * 2 + (r & 1);
            bool top = (r < 2);
            bool vi = top ? vA : vB;
            float L = -1e30f;
            if (vi && j < 49) {
                int rj = j / WSZ, cj = j - rj * WSZ;
                int ri = top ? riA : riB, ci = top ? ciA : ciB;
                int gi = top ? giA : giB;
                float qs = top ? qsA : qsB;
                int idx = (ri - rj + 6) * 13 + (ci - cj + 6);
                float mval = (gi != sgid[j]) ? -100.f : 0.f;
                L = acc[n][r] * qs * kinv[j] + stab[idx] + mval;
            }
            acc[n][r] = L;
        }
    }

    float mA = -1e30f, mB = -1e30f;
#pragma unroll
    for (int n = 0; n < 8; n++) {
        mA = fmaxf(mA, fmaxf(acc[n][0], acc[n][1]));
        mB = fmaxf(mB, fmaxf(acc[n][2], acc[n][3]));
    }
    mA = fmaxf(mA, __shfl_xor_sync(0xffffffffu, mA, 1));
    mA = fmaxf(mA, __shfl_xor_sync(0xffffffffu, mA, 2));
    mB = fmaxf(mB, __shfl_xor_sync(0xffffffffu, mB, 1));
    mB = fmaxf(mB, __shfl_xor_sync(0xffffffffu, mB, 2));

    float sA = 0.f, sB = 0.f;
#pragma unroll
    for (int n = 0; n < 8; n++) {
        float e0 = __expf(acc[n][0] - mA); acc[n][0] = e0; sA += e0;
        float e1 = __expf(acc[n][1] - mA); acc[n][1] = e1; sA += e1;
        float e2 = __expf(acc[n][2] - mB); acc[n][2] = e2; sB += e2;
        float e3 = __expf(acc[n][3] - mB); acc[n][3] = e3; sB += e3;
    }
    sA += __shfl_xor_sync(0xffffffffu, sA, 1);
    sA += __shfl_xor_sync(0xffffffffu, sA, 2);
    sB += __shfl_xor_sync(0xffffffffu, sB, 1);
    sB += __shfl_xor_sync(0xffffffffu, sB, 2);
    float rA = 1.0f / sA, rB = 1.0f / sB;

#pragma unroll
    for (int n = 0; n < 8; n++) {
        int jc = n * 8 + tg * 2;
        sP[iA * 68 + jc]     = f2tff(acc[n][0] * rA);
        sP[iA * 68 + jc + 1] = f2tff(acc[n][1] * rA);
        sP[iB * 68 + jc]     = f2tff(acc[n][2] * rB);
        sP[iB * 68 + jc + 1] = f2tff(acc[n][3] * rB);
    }
    __syncthreads();

    // ---- PV : O rows [wr*16, +16), cols d 0..31 ----
    float o[4][4];
#pragma unroll
    for (int nt = 0; nt < 4; nt++)
#pragma unroll
        for (int r = 0; r < 4; r++) o[nt][r] = 0.f;

#pragma unroll
    for (int kk = 0; kk < 8; kk++) {
        int kb = kk * 8;
        unsigned a[4];
        a[0] = __float_as_uint(sP[iA * 68 + kb + tg]);
        a[1] = __float_as_uint(sP[iB * 68 + kb + tg]);
        a[2] = __float_as_uint(sP[iA * 68 + kb + tg + 4]);
        a[3] = __float_as_uint(sP[iB * 68 + kb + tg + 4]);
#pragma unroll
        for (int nt = 0; nt < 4; nt++) {
            unsigned b[2];
            b[0] = __float_as_uint(sVT[(nt * 8 + g) * 68 + kb + tg]);
            b[1] = __float_as_uint(sVT[(nt * 8 + g) * 68 + kb + tg + 4]);
            mma_tf32(o[nt], a, b);
        }
    }

    if (vA) {
        size_t ob = ((size_t)(w * NTOK + iA)) * CDIM + h * HDIM;
#pragma unroll
        for (int nt = 0; nt < 4; nt++)
            *(float2*)&g_attnout[ob + nt * 8 + tg * 2] = make_float2(o[nt][0], o[nt][1]);
    }
    if (vB) {
        size_t ob = ((size_t)(w * NTOK + iB)) * CDIM + h * HDIM;
#pragma unroll
        for (int nt = 0; nt < 4; nt++)
            *(float2*)&g_attnout[ob + nt * 8 + tg * 2] = make_float2(o[nt][2], o[nt][3]);
    }
}

// ---------------- LN + residual: warp-per-row ----------------
__global__ void __launch_bounds__(256) ln1_kernel(
        const float* __restrict__ src, const float* __restrict__ x,
        const float* __restrict__ w, const float* __restrict__ b,
        float* __restrict__ x1) {
    int row = blockIdx.x * 8 + (threadIdx.x >> 5);
    int lane = threadIdx.x & 31;
    const float* s = src + (size_t)row * CDIM;
    float v[6];
    float sum = 0.f, sq = 0.f;
#pragma unroll
    for (int c = 0; c < 6; c++) {
        v[c] = s[lane + c * 32];
        sum += v[c]; sq = fmaf(v[c], v[c], sq);
    }
#pragma unroll
    for (int o = 16; o; o >>= 1) {
        sum += __shfl_xor_sync(0xffffffffu, sum, o);
        sq  += __shfl_xor_sync(0xffffffffu, sq, o);
    }
    float mean = sum * (1.0f / CDIM);
    float rstd = rsqrtf(sq * (1.0f / CDIM) - mean * mean + 1e-5f);

    int wv = row / NTOK, tk = row - wv * NTOK;
    int bb = wv >> 6, win = wv & 63;
    int r = tk / WSZ, c = tk - r * WSZ;
    int hp = (win >> 3) * WSZ + r + 3; if (hp >= IMG) hp -= IMG;
    int wpc = (win & 7) * WSZ + c + 3; if (wpc >= IMG) wpc -= IMG;
    size_t idx = ((size_t)((bb * IMG + hp) * IMG + wpc)) * CDIM;
#pragma unroll
    for (int cc = 0; cc < 6; cc++) {
        int t = lane + cc * 32;
        float y = (v[cc] - mean) * rstd * w[t] + b[t];
        x1[idx + t] = x[idx + t] + y;
    }
}

__global__ void __launch_bounds__(256) ln2_kernel(
        const float* __restrict__ src, const float* __restrict__ x1,
        const float* __restrict__ w, const float* __restrict__ b,
        float* __restrict__ out) {
    int row = blockIdx.x * 8 + (threadIdx.x >> 5);
    int lane = threadIdx.x & 31;
    const float* s = src + (size_t)row * CDIM;
    float v[6];
    float sum = 0.f, sq = 0.f;
#pragma unroll
    for (int c = 0; c < 6; c++) {
        v[c] = s[lane + c * 32];
        sum += v[c]; sq = fmaf(v[c], v[c], sq);
    }
#pragma unroll
    for (int o = 16; o; o >>= 1) {
        sum += __shfl_xor_sync(0xffffffffu, sum, o);
        sq  += __shfl_xor_sync(0xffffffffu, sq, o);
    }
    float mean = sum * (1.0f / CDIM);
    float rstd = rsqrtf(sq * (1.0f / CDIM) - mean * mean + 1e-5f);
    size_t idx = (size_t)row * CDIM;
#pragma unroll
    for (int cc = 0; cc < 6; cc++) {
        int t = lane + cc * 32;
        float y = (v[cc] - mean) * rstd * w[t] + b[t];
        out[idx + t] = x1[idx + t] + y;
    }
}

// ---------------- launcher ----------------
extern "C" void kernel_launch(void* const* d_in, const int* in_sizes, int n_in,
                              void* d_out, int out_size) {
    const float* x       = (const float*)d_in[0];
    const float* qkv_w   = (const float*)d_in[1];
    const float* qkv_b   = (const float*)d_in[2];
    const float* proj_w  = (const float*)d_in[3];
    const float* proj_b  = (const float*)d_in[4];
    const float* lscale  = (const float*)d_in[5];
    const float* cpb_w1  = (const float*)d_in[6];
    const float* cpb_b1  = (const float*)d_in[7];
    const float* cpb_w2  = (const float*)d_in[8];
    const float* n1w     = (const float*)d_in[9];
    const float* n1b     = (const float*)d_in[10];
    const float* n2w     = (const float*)d_in[11];
    const float* n2b     = (const float*)d_in[12];
    const float* fc1_w   = (const float*)d_in[13];
    const float* fc1_b   = (const float*)d_in[14];
    const float* fc2_w   = (const float*)d_in[15];
    const float* fc2_b   = (const float*)d_in[16];
    float* out = (float*)d_out;

    float *p_attn, *p_scr, *p_x1, *p_hid;
    cudaGetSymbolAddress((void**)&p_attn, g_attnout);
    cudaGetSymbolAddress((void**)&p_scr,  g_scratch);
    cudaGetSymbolAddress((void**)&p_x1,   g_x1);
    cudaGetSymbolAddress((void**)&p_hid,  g_hidden);

    cudaFuncSetAttribute(attn_kernel,
        cudaFuncAttributeMaxDynamicSharedMemorySize, ATT_SMEM_BYTES);

    const int MT = TOK / 128;  // 784

    tab_kernel<<<1, 256>>>(cpb_w1, cpb_b1, cpb_w2, lscale);
    tgemm_kernel<1, 0, 1><<<dim3(6, MT), 192>>>(x, qkv_w, qkv_b, nullptr, CDIM, 576);
    attn_kernel<<<BWIN * NHEAD, 128, ATT_SMEM_BYTES>>>();
    tgemm_kernel<0, 0, 0><<<dim3(2, MT), 192>>>(p_attn, proj_w, proj_b, p_scr, CDIM, CDIM);
    ln1_kernel<<<TOK / 8, 256>>>(p_scr, x, n1w, n1b, p_x1);
    tgemm_kernel<0, 1, 0><<<dim3(8, MT), 192>>>(p_x1, fc1_w, fc1_b, p_hid, CDIM, MLPH);
    tgemm_kernel<0, 0, 0><<<dim3(2, MT), 192>>>(p_hid, fc2_w, fc2_b, p_scr, MLPH, CDIM);
    ln2_kernel<<<TOK / 8, 256>>>(p_scr, p_x1, n2w, n2b, out);
}

// round 11
// speedup vs baseline: 3.0270x; 1.0074x over previous
#include <cuda_runtime.h>
#include <cuda_bf16.h>
#include <math.h>

// ---------------- problem constants ----------------
#define BATCH 32
#define IMG   56
#define CDIM  192
#define NHEAD 6
#define HDIM  32
#define WSZ   7
#define NTOK  49
#define NWIN  64
#define BWIN  (BATCH*NWIN)  // 2048
#define TOK   (BWIN*NTOK)   // 100352
#define MLPH  768

#define QKVSZ (BWIN*NHEAD*NTOK*HDIM)

// ---------------- scratch ----------------
__device__ float g_qkv[3u * (size_t)QKVSZ];
__device__ float g_attnout[(size_t)TOK * CDIM];
__device__ float g_x1[(size_t)BATCH * IMG * IMG * CDIM];
__device__ float g_hidden[(size_t)TOK * MLPH];
__device__ float g_tabsig[169 * NHEAD];
__device__ float g_scale[NHEAD];

// ---------------- CPB table + scale (tiny) ----------------
__global__ void tab_kernel(const float* __restrict__ w1, const float* __restrict__ b1,
                           const float* __restrict__ w2, const float* __restrict__ ls) {
    __shared__ float sW1[1024];
    __shared__ float sB1[512];
    __shared__ float sW2[NHEAD * 512];
    int tid = threadIdx.x;
    for (int i = tid; i < 1024; i += blockDim.x) sW1[i] = w1[i];
    for (int i = tid; i < 512;  i += blockDim.x) sB1[i] = b1[i];
    for (int i = tid; i < NHEAD * 512; i += blockDim.x) sW2[i] = w2[i];
    __syncthreads();

    if (tid < 169) {
        int i = tid / 13, j = tid % 13;
        float vh = (float)(i - 6) * (7.0f / 6.0f);
        float vw = (float)(j - 6) * (7.0f / 6.0f);
        const float inv_log2_7 = 0.35620719f;
        float th = copysignf(log2f(fabsf(vh) + 1.0f) * inv_log2_7, vh);
        float tw = copysignf(log2f(fabsf(vw) + 1.0f) * inv_log2_7, vw);
        float acc[NHEAD];
#pragma unroll
        for (int h = 0; h < NHEAD; h++) acc[h] = 0.f;
        for (int jj = 0; jj < 512; jj++) {
            float hval = fmaf(th, sW1[2 * jj], fmaf(tw, sW1[2 * jj + 1], sB1[jj]));
            hval = (hval > 0.f) ? hval : 0.01f * hval;
#pragma unroll
            for (int h = 0; h < NHEAD; h++) acc[h] = fmaf(hval, sW2[h * 512 + jj], acc[h]);
        }
#pragma unroll
        for (int h = 0; h < NHEAD; h++)
            g_tabsig[tid * NHEAD + h] = 14.f / (1.f + expf(-acc[h]));
    }
    if (tid < NHEAD) g_scale[tid] = expf(fminf(ls[tid], logf(100.f)));
}

// ---------------- tf32 helpers ----------------
__device__ __forceinline__ unsigned f2tf(float f) {
    unsigned r; asm("cvt.rna.tf32.f32 %0, %1;" : "=r"(r) : "f"(f)); return r;
}
__device__ __forceinline__ float f2tff(float f) {
    return __uint_as_float(f2tf(f));
}
__device__ __forceinline__ void mma_tf32(float* c, const unsigned* a, const unsigned* b) {
    asm volatile("mma.sync.aligned.m16n8k8.row.col.f32.tf32.tf32.f32 "
        "{%0,%1,%2,%3}, {%4,%5,%6,%7}, {%8,%9}, {%0,%1,%2,%3};"
        : "+f"(c[0]), "+f"(c[1]), "+f"(c[2]), "+f"(c[3])
        : "r"(a[0]), "r"(a[1]), "r"(a[2]), "r"(a[3]), "r"(b[0]), "r"(b[1]));
}

#define ASTRIDE 20

__device__ __forceinline__ size_t gather_off(int m) {
    int wv = m / NTOK, tk = m - wv * NTOK;
    int bb = wv >> 6, win = wv & 63;
    int r = tk / WSZ, c = tk - r * WSZ;
    int hp = (win >> 3) * WSZ + r + 3; if (hp >= IMG) hp -= IMG;
    int wp = (win & 7) * WSZ + c + 3;  if (wp >= IMG) wp -= IMG;
    return ((size_t)((bb * IMG + hp) * IMG + wp)) * CDIM;
}

// ---------------- tf32 GEMM: block 128x192, 8 warps of 64x48 ----------------
// GATHER: A rows gathered from image via swin shift map.
// ACT: 1 = exact GELU on output.
// SCATTER: epilogue writes q/k/v head-major (qkv GEMM).
// LNF: 0 none; 1 = LN + residual-from-gather (proj->x1); 2 = LN + residual linear (fc2->out).
template <int GATHER, int ACT, int SCATTER, int LNF>
__global__ void __launch_bounds__(256) tgemm_kernel(
        const float* __restrict__ A, const float* __restrict__ Wg,
        const float* __restrict__ bias, float* __restrict__ out,
        const float* __restrict__ lnw, const float* __restrict__ lnb,
        const float* __restrict__ res,
        int K, int Ndim) {
    __shared__ unsigned As[128 * ASTRIDE];
    __shared__ unsigned Bs[192 * ASTRIDE];
    int tid = threadIdx.x;
    int m0 = blockIdx.y * 128, n0 = blockIdx.x * 192;

    // A tasks: 2 per thread; B tasks: 3 per thread
    const float* arowp[2];
    int aoff[2], akc[2];
#pragma unroll
    for (int s = 0; s < 2; s++) {
        int v = tid + s * 256;
        int row = v >> 2;
        akc[s] = (v & 3) * 4;
        aoff[s] = row * ASTRIDE + akc[s];
        arowp[s] = GATHER ? (A + gather_off(m0 + row)) : (A + (size_t)(m0 + row) * K);
    }
    const float* browp[3];
    int boff[3], bkc[3];
#pragma unroll
    for (int s = 0; s < 3; s++) {
        int v = tid + s * 256;
        int row = v >> 2;
        bkc[s] = (v & 3) * 4;
        boff[s] = row * ASTRIDE + bkc[s];
        browp[s] = Wg + (size_t)(n0 + row) * K;
    }

    int lane = tid & 31, w = tid >> 5;
    int wm = w & 1, wn = w >> 1;          // 2(M) x 4(N), warp tile 64x48
    int g = lane >> 2, tg = lane & 3;

    float acc[4][6][4];
#pragma unroll
    for (int i = 0; i < 4; i++)
#pragma unroll
        for (int j = 0; j < 6; j++)
#pragma unroll
            for (int r = 0; r < 4; r++) acc[i][j][r] = 0.f;

    float4 pa[2], pb[3];
#pragma unroll
    for (int s = 0; s < 2; s++) pa[s] = *(const float4*)(arowp[s] + akc[s]);
#pragma unroll
    for (int s = 0; s < 3; s++) pb[s] = *(const float4*)(browp[s] + bkc[s]);

    for (int k0 = 0; k0 < K; k0 += 16) {
        __syncthreads();
#pragma unroll
        for (int s = 0; s < 2; s++)
            *(uint4*)&As[aoff[s]] = make_uint4(f2tf(pa[s].x), f2tf(pa[s].y), f2tf(pa[s].z), f2tf(pa[s].w));
#pragma unroll
        for (int s = 0; s < 3; s++)
            *(uint4*)&Bs[boff[s]] = make_uint4(f2tf(pb[s].x), f2tf(pb[s].y), f2tf(pb[s].z), f2tf(pb[s].w));
        __syncthreads();

        int kn = k0 + 16;
        if (kn < K) {
#pragma unroll
            for (int s = 0; s < 2; s++) pa[s] = *(const float4*)(arowp[s] + kn + akc[s]);
#pragma unroll
            for (int s = 0; s < 3; s++) pb[s] = *(const float4*)(browp[s] + kn + bkc[s]);
        }

#pragma unroll
        for (int kk = 0; kk < 16; kk += 8) {
            unsigned afr[4][4], bfr[6][2];
#pragma unroll
            for (int i = 0; i < 4; i++) {
                int mrow = wm * 64 + i * 16 + g;
                afr[i][0] = As[mrow * ASTRIDE + kk + tg];
                afr[i][1] = As[(mrow + 8) * ASTRIDE + kk + tg];
                afr[i][2] = As[mrow * ASTRIDE + kk + tg + 4];
                afr[i][3] = As[(mrow + 8) * ASTRIDE + kk + tg + 4];
            }
#pragma unroll
            for (int j = 0; j < 6; j++) {
                int ncol = wn * 48 + j * 8 + g;
                bfr[j][0] = Bs[ncol * ASTRIDE + kk + tg];
                bfr[j][1] = Bs[ncol * ASTRIDE + kk + tg + 4];
            }
#pragma unroll
            for (int i = 0; i < 4; i++)
#pragma unroll
                for (int j = 0; j < 6; j++)
                    mma_tf32(acc[i][j], afr[i], bfr[j]);
        }
    }

    if (LNF == 0) {
        // plain / scatter / gelu epilogue
#pragma unroll
        for (int i = 0; i < 4; i++) {
            int rowb = m0 + wm * 64 + i * 16 + g;
#pragma unroll
            for (int j = 0; j < 6; j++) {
                int colb = n0 + wn * 48 + j * 8 + tg * 2;
#pragma unroll
                for (int r = 0; r < 4; r++) {
                    int rr = rowb + (r >> 1) * 8;
                    int cc = colb + (r & 1);
                    float v = acc[i][j][r] + bias[cc];
                    if (ACT == 1) v = 0.5f * v * (1.0f + erff(v * 0.70710678118654752f));
                    if (SCATTER) {
                        int which = cc / CDIM;
                        int rem = cc - which * CDIM;
                        int head = rem >> 5, dd = rem & 31;
                        int wv = rr / NTOK, tk = rr - wv * NTOK;
                        g_qkv[(size_t)which * QKVSZ +
                              ((size_t)(wv * NHEAD + head) * NTOK + tk) * HDIM + dd] = v;
                    } else {
                        out[(size_t)rr * Ndim + cc] = v;
                    }
                }
            }
        }
    } else {
        // fused LayerNorm + residual epilogue (N tile == full C == 192, n0 == 0)
        __syncthreads();                       // smem no longer needed for tiles
        float* spart = (float*)As;             // [128 rows][4 wn][sum,sq]

        float vsum[4][2], vsq[4][2];
#pragma unroll
        for (int i = 0; i < 4; i++) { vsum[i][0] = vsum[i][1] = 0.f; vsq[i][0] = vsq[i][1] = 0.f; }
#pragma unroll
        for (int i = 0; i < 4; i++)
#pragma unroll
            for (int j = 0; j < 6; j++)
#pragma unroll
                for (int r = 0; r < 4; r++) {
                    int cc = wn * 48 + j * 8 + tg * 2 + (r & 1);
                    float v = acc[i][j][r] + bias[cc];
                    acc[i][j][r] = v;
                    vsum[i][r >> 1] += v;
                    vsq[i][r >> 1] = fmaf(v, v, vsq[i][r >> 1]);
                }
        // reduce over tg (lane bits 0,1)
#pragma unroll
        for (int i = 0; i < 4; i++)
#pragma unroll
            for (int h2 = 0; h2 < 2; h2++) {
                float s = vsum[i][h2], q = vsq[i][h2];
                s += __shfl_xor_sync(0xffffffffu, s, 1);
                s += __shfl_xor_sync(0xffffffffu, s, 2);
                q += __shfl_xor_sync(0xffffffffu, q, 1);
                q += __shfl_xor_sync(0xffffffffu, q, 2);
                if (tg == 0) {
                    int row = wm * 64 + i * 16 + g + 8 * h2;
                    spart[row * 8 + wn * 2]     = s;
                    spart[row * 8 + wn * 2 + 1] = q;
                }
            }
        __syncthreads();

        float mean[4][2], rstd[4][2];
#pragma unroll
        for (int i = 0; i < 4; i++)
#pragma unroll
            for (int h2 = 0; h2 < 2; h2++) {
                int row = wm * 64 + i * 16 + g + 8 * h2;
                float s = spart[row * 8 + 0] + spart[row * 8 + 2] +
                          spart[row * 8 + 4] + spart[row * 8 + 6];
                float q = spart[row * 8 + 1] + spart[row * 8 + 3] +
                          spart[row * 8 + 5] + spart[row * 8 + 7];
                float m = s * (1.0f / CDIM);
                mean[i][h2] = m;
                rstd[i][h2] = rsqrtf(q * (1.0f / CDIM) - m * m + 1e-5f);
            }

#pragma unroll
        for (int i = 0; i < 4; i++)
#pragma unroll
            for (int h2 = 0; h2 < 2; h2++) {
                int rr = m0 + wm * 64 + i * 16 + g + 8 * h2;
                size_t off = (LNF == 1) ? gather_off(rr) : (size_t)rr * CDIM;
                float m = mean[i][h2], rs = rstd[i][h2];
#pragma unroll
                for (int j = 0; j < 6; j++) {
                    int cc = wn * 48 + j * 8 + tg * 2;
                    float v0 = acc[i][j][h2 * 2 + 0];
                    float v1 = acc[i][j][h2 * 2 + 1];
                    float y0 = (v0 - m) * rs * lnw[cc]     + lnb[cc];
                    float y1 = (v1 - m) * rs * lnw[cc + 1] + lnb[cc + 1];
                    float2 rv = *(const float2*)(res + off + cc);
                    *(float2*)(out + off + cc) = make_float2(rv.x + y0, rv.y + y1);
                }
            }
    }
}

// ---------------- tensor-core attention (unchanged from R10) ----------------
#define OQH 0
#define OQL 2304
#define OKH 4608
#define OKL 6912
#define OVT 9216
#define OP  11392
#define OQI 15744
#define OKI 15808
#define OTAB 15872
#define OGID 16048
#define ATT_SMEM_FLOATS 16112
#define ATT_SMEM_BYTES (ATT_SMEM_FLOATS * 4)

__global__ void __launch_bounds__(128) attn_kernel() {
    extern __shared__ float smx[];
    float* sQh = smx + OQH;
    float* sQl = smx + OQL;
    float* sKh = smx + OKH;
    float* sKl = smx + OKL;
    float* sVT = smx + OVT;
    float* sP  = smx + OP;
    float* qinv = smx + OQI;
    float* kinv = smx + OKI;
    float* stab = smx + OTAB;
    int*   sgid = (int*)(smx + OGID);

    int blk = blockIdx.x;
    int w = blk / NHEAD;
    int h = blk - w * NHEAD;
    int tid = threadIdx.x;
    int lane = tid & 31, wr = tid >> 5;
    int g = lane >> 2, tg = lane & 3;

    size_t base = ((size_t)(w * NHEAD + h) * NTOK) * HDIM;
    const float* qp = g_qkv + base;
    const float* kp = g_qkv + (size_t)QKVSZ + base;
    const float* vp = g_qkv + 2 * (size_t)QKVSZ + base;

    for (int i = tid; i < 15 * 32; i += 128) {
        int r = 49 + (i >> 5), c = i & 31;
        sQh[r * 36 + c] = 0.f; sQl[r * 36 + c] = 0.f;
        sKh[r * 36 + c] = 0.f; sKl[r * 36 + c] = 0.f;
    }
    for (int i = tid; i < 32 * 16; i += 128) {
        int d = i >> 4, j = 48 + (i & 15);
        sVT[d * 68 + j] = 0.f;
    }

    for (int idx = tid; idx < 392; idx += 128) {
        int r = idx >> 3, c4 = (idx & 7) * 4;
        float4 q = *(const float4*)(qp + r * 32 + c4);
        float4 k = *(const float4*)(kp + r * 32 + c4);
        float4 v = *(const float4*)(vp + r * 32 + c4);
        float qh0 = f2tff(q.x), qh1 = f2tff(q.y), qh2 = f2tff(q.z), qh3 = f2tff(q.w);
        sQh[r * 36 + c4 + 0] = qh0; sQl[r * 36 + c4 + 0] = f2tff(q.x - qh0);
        sQh[r * 36 + c4 + 1] = qh1; sQl[r * 36 + c4 + 1] = f2tff(q.y - qh1);
        sQh[r * 36 + c4 + 2] = qh2; sQl[r * 36 + c4 + 2] = f2tff(q.z - qh2);
        sQh[r * 36 + c4 + 3] = qh3; sQl[r * 36 + c4 + 3] = f2tff(q.w - qh3);
        float kh0 = f2tff(k.x), kh1 = f2tff(k.y), kh2 = f2tff(k.z), kh3 = f2tff(k.w);
        sKh[r * 36 + c4 + 0] = kh0; sKl[r * 36 + c4 + 0] = f2tff(k.x - kh0);
        sKh[r * 36 + c4 + 1] = kh1; sKl[r * 36 + c4 + 1] = f2tff(k.y - kh1);
        sKh[r * 36 + c4 + 2] = kh2; sKl[r * 36 + c4 + 2] = f2tff(k.z - kh2);
        sKh[r * 36 + c4 + 3] = kh3; sKl[r * 36 + c4 + 3] = f2tff(k.w - kh3);
        sVT[(c4 + 0) * 68 + r] = f2tff(v.x);
        sVT[(c4 + 1) * 68 + r] = f2tff(v.y);
        sVT[(c4 + 2) * 68 + r] = f2tff(v.z);
        sVT[(c4 + 3) * 68 + r] = f2tff(v.w);
    }
    for (int i = tid; i < 169; i += 128) stab[i] = g_tabsig[i * NHEAD + h];

    int win = w & 63;
    int wi = win >> 3, wj = win & 7;
    if (tid < 64) {
        int t = (tid < 49) ? tid : 48;
        int r = t / WSZ, c = t - r * WSZ;
        int sh = wi * WSZ + r, sw = wj * WSZ + c;
        int gh = (sh < 49) ? 0 : ((sh < 53) ? 1 : 2);
        int gw = (sw < 49) ? 0 : ((sw < 53) ? 1 : 2);
        sgid[tid] = gh * 3 + gw;
    }
    __syncthreads();

    if (tid < 49) {
        float s = 0.f;
#pragma unroll
        for (int d = 0; d < 32; d++) {
            float v = sQh[tid * 36 + d] + sQl[tid * 36 + d];
            s = fmaf(v, v, s);
        }
        qinv[tid] = 1.0f / fmaxf(sqrtf(s), 1e-12f);
    } else if (tid >= 64 && tid < 64 + 49) {
        int r = tid - 64;
        float s = 0.f;
#pragma unroll
        for (int d = 0; d < 32; d++) {
            float v = sKh[r * 36 + d] + sKl[r * 36 + d];
            s = fmaf(v, v, s);
        }
        kinv[r] = 1.0f / fmaxf(sqrtf(s), 1e-12f);
    }
    __syncthreads();

    float acc[8][4];
#pragma unroll
    for (int n = 0; n < 8; n++)
#pragma unroll
        for (int r = 0; r < 4; r++) acc[n][r] = 0.f;

    int arow = wr * 16 + g;
#pragma unroll
    for (int kk = 0; kk < 4; kk++) {
        int kb = kk * 8;
        unsigned ah[4], al[4];
        ah[0] = __float_as_uint(sQh[arow * 36 + kb + tg]);
        ah[1] = __float_as_uint(sQh[(arow + 8) * 36 + kb + tg]);
        ah[2] = __float_as_uint(sQh[arow * 36 + kb + tg + 4]);
        ah[3] = __float_as_uint(sQh[(arow + 8) * 36 + kb + tg + 4]);
        al[0] = __float_as_uint(sQl[arow * 36 + kb + tg]);
        al[1] = __float_as_uint(sQl[(arow + 8) * 36 + kb + tg]);
        al[2] = __float_as_uint(sQl[arow * 36 + kb + tg + 4]);
        al[3] = __float_as_uint(sQl[(arow + 8) * 36 + kb + tg + 4]);
#pragma unroll
        for (int n = 0; n < 8; n++) {
            int bj = n * 8 + g;
            unsigned bh[2], bl[2];
            bh[0] = __float_as_uint(sKh[bj * 36 + kb + tg]);
            bh[1] = __float_as_uint(sKh[bj * 36 + kb + tg + 4]);
            bl[0] = __float_as_uint(sKl[bj * 36 + kb + tg]);
            bl[1] = __float_as_uint(sKl[bj * 36 + kb + tg + 4]);
            mma_tf32(acc[n], al, bh);
            mma_tf32(acc[n], ah, bl);
            mma_tf32(acc[n], ah, bh);
        }
    }

    float scale = g_scale[h];
    int iA = wr * 16 + g, iB = iA + 8;
    bool vA = (iA < 49), vB = (iB < 49);
    int riA = 0, ciA = 0, giA = 0, riB = 0, ciB = 0, giB = 0;
    float qsA = 0.f, qsB = 0.f;
    if (vA) { riA = iA / WSZ; ciA = iA - riA * WSZ; giA = sgid[iA]; qsA = qinv[iA] * scale; }
    if (vB) { riB = iB / WSZ; ciB = iB - riB * WSZ; giB = sgid[iB]; qsB = qinv[iB] * scale; }

#pragma unroll
    for (int n = 0; n < 8; n++) {
#pragma unroll
        for (int r = 0; r < 4; r++) {
            int j = n * 8 + tg * 2 + (r & 1);
            bool top = (r < 2);
            bool vi = top ? vA : vB;
            float L = -1e30f;
            if (vi && j < 49) {
                int rj = j / WSZ, cj = j - rj * WSZ;
                int ri = top ? riA : riB, ci = top ? ciA : ciB;
                int gi = top ? giA : giB;
                float qs = top ? qsA : qsB;
                int idx = (ri - rj + 6) * 13 + (ci - cj + 6);
                float mval = (gi != sgid[j]) ? -100.f : 0.f;
                L = acc[n][r] * qs * kinv[j] + stab[idx] + mval;
            }
            acc[n][r] = L;
        }
    }

    float mA = -1e30f, mB = -1e30f;
#pragma unroll
    for (int n = 0; n < 8; n++) {
        mA = fmaxf(mA, fmaxf(acc[n][0], acc[n][1]));
        mB = fmaxf(mB, fmaxf(acc[n][2], acc[n][3]));
    }
    mA = fmaxf(mA, __shfl_xor_sync(0xffffffffu, mA, 1));
    mA = fmaxf(mA, __shfl_xor_sync(0xffffffffu, mA, 2));
    mB = fmaxf(mB, __shfl_xor_sync(0xffffffffu, mB, 1));
    mB = fmaxf(mB, __shfl_xor_sync(0xffffffffu, mB, 2));

    float sA = 0.f, sB = 0.f;
#pragma unroll
    for (int n = 0; n < 8; n++) {
        float e0 = __expf(acc[n][0] - mA); acc[n][0] = e0; sA += e0;
        float e1 = __expf(acc[n][1] - mA); acc[n][1] = e1; sA += e1;
        float e2 = __expf(acc[n][2] - mB); acc[n][2] = e2; sB += e2;
        float e3 = __expf(acc[n][3] - mB); acc[n][3] = e3; sB += e3;
    }
    sA += __shfl_xor_sync(0xffffffffu, sA, 1);
    sA += __shfl_xor_sync(0xffffffffu, sA, 2);
    sB += __shfl_xor_sync(0xffffffffu, sB, 1);
    sB += __shfl_xor_sync(0xffffffffu, sB, 2);
    float rA = 1.0f / sA, rB = 1.0f / sB;

#pragma unroll
    for (int n = 0; n < 8; n++) {
        int jc = n * 8 + tg * 2;
        sP[iA * 68 + jc]     = f2tff(acc[n][0] * rA);
        sP[iA * 68 + jc + 1] = f2tff(acc[n][1] * rA);
        sP[iB * 68 + jc]     = f2tff(acc[n][2] * rB);
        sP[iB * 68 + jc + 1] = f2tff(acc[n][3] * rB);
    }
    __syncthreads();

    float o[4][4];
#pragma unroll
    for (int nt = 0; nt < 4; nt++)
#pragma unroll
        for (int r = 0; r < 4; r++) o[nt][r] = 0.f;

#pragma unroll
    for (int kk = 0; kk < 8; kk++) {
        int kb = kk * 8;
        unsigned a[4];
        a[0] = __float_as_uint(sP[iA * 68 + kb + tg]);
        a[1] = __float_as_uint(sP[iB * 68 + kb + tg]);
        a[2] = __float_as_uint(sP[iA * 68 + kb + tg + 4]);
        a[3] = __float_as_uint(sP[iB * 68 + kb + tg + 4]);
#pragma unroll
        for (int nt = 0; nt < 4; nt++) {
            unsigned b[2];
            b[0] = __float_as_uint(sVT[(nt * 8 + g) * 68 + kb + tg]);
            b[1] = __float_as_uint(sVT[(nt * 8 + g) * 68 + kb + tg + 4]);
            mma_tf32(o[nt], a, b);
        }
    }

    if (vA) {
        size_t ob = ((size_t)(w * NTOK + iA)) * CDIM + h * HDIM;
#pragma unroll
        for (int nt = 0; nt < 4; nt++)
            *(float2*)&g_attnout[ob + nt * 8 + tg * 2] = make_float2(o[nt][0], o[nt][1]);
    }
    if (vB) {
        size_t ob = ((size_t)(w * NTOK + iB)) * CDIM + h * HDIM;
#pragma unroll
        for (int nt = 0; nt < 4; nt++)
            *(float2*)&g_attnout[ob + nt * 8 + tg * 2] = make_float2(o[nt][2], o[nt][3]);
    }
}

// ---------------- launcher ----------------
extern "C" void kernel_launch(void* const* d_in, const int* in_sizes, int n_in,
                              void* d_out, int out_size) {
    const float* x       = (const float*)d_in[0];
    const float* qkv_w   = (const float*)d_in[1];
    const float* qkv_b   = (const float*)d_in[2];
    const float* proj_w  = (const float*)d_in[3];
    const float* proj_b  = (const float*)d_in[4];
    const float* lscale  = (const float*)d_in[5];
    const float* cpb_w1  = (const float*)d_in[6];
    const float* cpb_b1  = (const float*)d_in[7];
    const float* cpb_w2  = (const float*)d_in[8];
    const float* n1w     = (const float*)d_in[9];
    const float* n1b     = (const float*)d_in[10];
    const float* n2w     = (const float*)d_in[11];
    const float* n2b     = (const float*)d_in[12];
    const float* fc1_w   = (const float*)d_in[13];
    const float* fc1_b   = (const float*)d_in[14];
    const float* fc2_w   = (const float*)d_in[15];
    const float* fc2_b   = (const float*)d_in[16];
    float* out = (float*)d_out;

    float *p_attn, *p_x1, *p_hid;
    cudaGetSymbolAddress((void**)&p_attn, g_attnout);
    cudaGetSymbolAddress((void**)&p_x1,   g_x1);
    cudaGetSymbolAddress((void**)&p_hid,  g_hidden);

    cudaFuncSetAttribute(attn_kernel,
        cudaFuncAttributeMaxDynamicSharedMemorySize, ATT_SMEM_BYTES);

    const int MT = TOK / 128;  // 784

    tab_kernel<<<1, 256>>>(cpb_w1, cpb_b1, cpb_w2, lscale);
    // QKV: gather A from x, scatter epilogue to g_qkv. N=576 -> 3 tiles of 192
    tgemm_kernel<1, 0, 1, 0><<<dim3(3, MT), 256>>>(
        x, qkv_w, qkv_b, nullptr, nullptr, nullptr, nullptr, CDIM, 576);
    attn_kernel<<<BWIN * NHEAD, 128, ATT_SMEM_BYTES>>>();
    // proj + LN1 + residual(x, gathered) -> x1
    tgemm_kernel<0, 0, 0, 1><<<dim3(1, MT), 256>>>(
        p_attn, proj_w, proj_b, p_x1, n1w, n1b, x, CDIM, CDIM);
    // fc1 + GELU -> hidden. N=768 -> 4 tiles of 192
    tgemm_kernel<0, 1, 0, 0><<<dim3(4, MT), 256>>>(
        p_x1, fc1_w, fc1_b, p_hid, nullptr, nullptr, nullptr, CDIM, MLPH);
    // fc2 + LN2 + residual(x1) -> out
    tgemm_kernel<0, 0, 0, 2><<<dim3(1, MT), 256>>>(
        p_hid, fc2_w, fc2_b, out, n2w, n2b, p_x1, MLPH, CDIM);
}

// round 13
// speedup vs baseline: 3.1741x; 1.0486x over previous
#include <cuda_runtime.h>
#include <cuda_bf16.h>
#include <math.h>

// ---------------- problem constants ----------------
#define BATCH 32
#define IMG   56
#define CDIM  192
#define NHEAD 6
#define HDIM  32
#define WSZ   7
#define NTOK  49
#define NWIN  64
#define BWIN  (BATCH*NWIN)  // 2048
#define TOK   (BWIN*NTOK)   // 100352
#define MLPH  768

#define QKVSZ (BWIN*NHEAD*NTOK*HDIM)

// ---------------- scratch ----------------
__device__ float g_qkv[3u * (size_t)QKVSZ];
__device__ float g_attnout[(size_t)TOK * CDIM];
__device__ float g_x1[(size_t)BATCH * IMG * IMG * CDIM];
__device__ float g_hidden[(size_t)TOK * MLPH];
__device__ float g_tabsig[169 * NHEAD];
__device__ float g_scale[NHEAD];

// ---------------- CPB table + scale (tiny) ----------------
__global__ void tab_kernel(const float* __restrict__ w1, const float* __restrict__ b1,
                           const float* __restrict__ w2, const float* __restrict__ ls) {
    __shared__ float sW1[1024];
    __shared__ float sB1[512];
    __shared__ float sW2[NHEAD * 512];
    int tid = threadIdx.x;
    for (int i = tid; i < 1024; i += blockDim.x) sW1[i] = w1[i];
    for (int i = tid; i < 512;  i += blockDim.x) sB1[i] = b1[i];
    for (int i = tid; i < NHEAD * 512; i += blockDim.x) sW2[i] = w2[i];
    __syncthreads();

    if (tid < 169) {
        int i = tid / 13, j = tid % 13;
        float vh = (float)(i - 6) * (7.0f / 6.0f);
        float vw = (float)(j - 6) * (7.0f / 6.0f);
        const float inv_log2_7 = 0.35620719f;
        float th = copysignf(log2f(fabsf(vh) + 1.0f) * inv_log2_7, vh);
        float tw = copysignf(log2f(fabsf(vw) + 1.0f) * inv_log2_7, vw);
        float acc[NHEAD];
#pragma unroll
        for (int h = 0; h < NHEAD; h++) acc[h] = 0.f;
        for (int jj = 0; jj < 512; jj++) {
            float hval = fmaf(th, sW1[2 * jj], fmaf(tw, sW1[2 * jj + 1], sB1[jj]));
            hval = (hval > 0.f) ? hval : 0.01f * hval;
#pragma unroll
            for (int h = 0; h < NHEAD; h++) acc[h] = fmaf(hval, sW2[h * 512 + jj], acc[h]);
        }
#pragma unroll
        for (int h = 0; h < NHEAD; h++)
            g_tabsig[tid * NHEAD + h] = 14.f / (1.f + expf(-acc[h]));
    }
    if (tid < NHEAD) g_scale[tid] = expf(fminf(ls[tid], logf(100.f)));
}

// ---------------- tf32 helpers ----------------
__device__ __forceinline__ unsigned f2tf(float f) {
    unsigned r; asm("cvt.rna.tf32.f32 %0, %1;" : "=r"(r) : "f"(f)); return r;
}
__device__ __forceinline__ float f2tff(float f) {
    return __uint_as_float(f2tf(f));
}
__device__ __forceinline__ void mma_tf32(float* c, const unsigned* a, const unsigned* b) {
    asm volatile("mma.sync.aligned.m16n8k8.row.col.f32.tf32.tf32.f32 "
        "{%0,%1,%2,%3}, {%4,%5,%6,%7}, {%8,%9}, {%0,%1,%2,%3};"
        : "+f"(c[0]), "+f"(c[1]), "+f"(c[2]), "+f"(c[3])
        : "r"(a[0]), "r"(a[1]), "r"(a[2]), "r"(a[3]), "r"(b[0]), "r"(b[1]));
}

#define ASTRIDE 20

__device__ __forceinline__ size_t gather_off(int m) {
    int wv = m / NTOK, tk = m - wv * NTOK;
    int bb = wv >> 6, win = wv & 63;
    int r = tk / WSZ, c = tk - r * WSZ;
    int hp = (win >> 3) * WSZ + r + 3; if (hp >= IMG) hp -= IMG;
    int wp = (win & 7) * WSZ + c + 3;  if (wp >= IMG) wp -= IMG;
    return ((size_t)((bb * IMG + hp) * IMG + wp)) * CDIM;
}

// ---------------- tf32 GEMM: block 64x192, 8 warps of 32x48 ----------------
// Double-buffered smem, single __syncthreads per k-slab, 2 blocks/SM target.
// GATHER: A rows gathered from image via swin shift map.
// ACT: 1 = exact GELU on output.
// SCATTER: epilogue writes q/k/v head-major (qkv GEMM).
// LNF: 0 none; 1 = LN + residual-from-gather (proj->x1); 2 = LN + residual linear (fc2->out).
template <int GATHER, int ACT, int SCATTER, int LNF>
__global__ void __launch_bounds__(256, 2) tgemm_kernel(
        const float* __restrict__ A, const float* __restrict__ Wg,
        const float* __restrict__ bias, float* __restrict__ out,
        const float* __restrict__ lnw, const float* __restrict__ lnb,
        const float* __restrict__ res,
        int K, int Ndim) {
    __shared__ unsigned As[2][64 * ASTRIDE];
    __shared__ unsigned Bs[2][192 * ASTRIDE];
    int tid = threadIdx.x;
    int m0 = blockIdx.y * 64, n0 = blockIdx.x * 192;

    // A: 1 task/thread (64 rows x 4 kc = 256)
    int arow_ = tid >> 2;
    int akc = (tid & 3) * 4;
    int aoff = arow_ * ASTRIDE + akc;
    const float* arowp = GATHER ? (A + gather_off(m0 + arow_))
                                : (A + (size_t)(m0 + arow_) * K);
    // B: 3 tasks/thread (192 rows x 4 kc = 768)
    const float* browp[3];
    int boff[3], bkc[3];
#pragma unroll
    for (int s = 0; s < 3; s++) {
        int v = tid + s * 256;
        int row = v >> 2;
        bkc[s] = (v & 3) * 4;
        boff[s] = row * ASTRIDE + bkc[s];
        browp[s] = Wg + (size_t)(n0 + row) * K;
    }

    int lane = tid & 31, w = tid >> 5;
    int wm = w & 1, wn = w >> 1;          // 2(M) x 4(N), warp tile 32x48
    int g = lane >> 2, tg = lane & 3;

    float acc[2][6][4];
#pragma unroll
    for (int i = 0; i < 2; i++)
#pragma unroll
        for (int j = 0; j < 6; j++)
#pragma unroll
            for (int r = 0; r < 4; r++) acc[i][j][r] = 0.f;

    float4 pa, pb[3];
    pa = *(const float4*)(arowp + akc);
#pragma unroll
    for (int s = 0; s < 3; s++) pb[s] = *(const float4*)(browp[s] + bkc[s]);

    int buf = 0;
    for (int k0 = 0; k0 < K; k0 += 16) {
        *(uint4*)&As[buf][aoff] = make_uint4(f2tf(pa.x), f2tf(pa.y), f2tf(pa.z), f2tf(pa.w));
#pragma unroll
        for (int s = 0; s < 3; s++)
            *(uint4*)&Bs[buf][boff[s]] = make_uint4(f2tf(pb[s].x), f2tf(pb[s].y), f2tf(pb[s].z), f2tf(pb[s].w));
        __syncthreads();

        int kn = k0 + 16;
        if (kn < K) {
            pa = *(const float4*)(arowp + kn + akc);
#pragma unroll
            for (int s = 0; s < 3; s++) pb[s] = *(const float4*)(browp[s] + kn + bkc[s]);
        }

#pragma unroll
        for (int kk = 0; kk < 16; kk += 8) {
            unsigned afr[2][4], bfr[6][2];
#pragma unroll
            for (int i = 0; i < 2; i++) {
                int mrow = wm * 32 + i * 16 + g;
                afr[i][0] = As[buf][mrow * ASTRIDE + kk + tg];
                afr[i][1] = As[buf][(mrow + 8) * ASTRIDE + kk + tg];
                afr[i][2] = As[buf][mrow * ASTRIDE + kk + tg + 4];
                afr[i][3] = As[buf][(mrow + 8) * ASTRIDE + kk + tg + 4];
            }
#pragma unroll
            for (int j = 0; j < 6; j++) {
                int ncol = wn * 48 + j * 8 + g;
                bfr[j][0] = Bs[buf][ncol * ASTRIDE + kk + tg];
                bfr[j][1] = Bs[buf][ncol * ASTRIDE + kk + tg + 4];
            }
#pragma unroll
            for (int i = 0; i < 2; i++)
#pragma unroll
                for (int j = 0; j < 6; j++)
                    mma_tf32(acc[i][j], afr[i], bfr[j]);
        }
        buf ^= 1;
    }

    if (LNF == 0) {
#pragma unroll
        for (int i = 0; i < 2; i++) {
            int rowb = m0 + wm * 32 + i * 16 + g;
#pragma unroll
            for (int j = 0; j < 6; j++) {
                int colb = n0 + wn * 48 + j * 8 + tg * 2;
#pragma unroll
                for (int r = 0; r < 4; r++) {
                    int rr = rowb + (r >> 1) * 8;
                    int cc = colb + (r & 1);
                    float v = acc[i][j][r] + bias[cc];
                    if (ACT == 1) v = 0.5f * v * (1.0f + erff(v * 0.70710678118654752f));
                    if (SCATTER) {
                        int which = cc / CDIM;
                        int rem = cc - which * CDIM;
                        int head = rem >> 5, dd = rem & 31;
                        int wv = rr / NTOK, tk = rr - wv * NTOK;
                        g_qkv[(size_t)which * QKVSZ +
                              ((size_t)(wv * NHEAD + head) * NTOK + tk) * HDIM + dd] = v;
                    } else {
                        out[(size_t)rr * Ndim + cc] = v;
                    }
                }
            }
        }
    } else {
        // fused LayerNorm + residual epilogue (N tile == full C == 192, n0 == 0)
        __syncthreads();
        float* spart = (float*)As;             // [64 rows][4 wn][sum,sq]

        float vsum[2][2], vsq[2][2];
#pragma unroll
        for (int i = 0; i < 2; i++) { vsum[i][0] = vsum[i][1] = 0.f; vsq[i][0] = vsq[i][1] = 0.f; }
#pragma unroll
        for (int i = 0; i < 2; i++)
#pragma unroll
            for (int j = 0; j < 6; j++)
#pragma unroll
                for (int r = 0; r < 4; r++) {
                    int cc = wn * 48 + j * 8 + tg * 2 + (r & 1);
                    float v = acc[i][j][r] + bias[cc];
                    acc[i][j][r] = v;
                    vsum[i][r >> 1] += v;
                    vsq[i][r >> 1] = fmaf(v, v, vsq[i][r >> 1]);
                }
#pragma unroll
        for (int i = 0; i < 2; i++)
#pragma unroll
            for (int h2 = 0; h2 < 2; h2++) {
                float s = vsum[i][h2], q = vsq[i][h2];
                s += __shfl_xor_sync(0xffffffffu, s, 1);
                s += __shfl_xor_sync(0xffffffffu, s, 2);
                q += __shfl_xor_sync(0xffffffffu, q, 1);
                q += __shfl_xor_sync(0xffffffffu, q, 2);
                if (tg == 0) {
                    int row = wm * 32 + i * 16 + g + 8 * h2;
                    spart[row * 8 + wn * 2]     = s;
                    spart[row * 8 + wn * 2 + 1] = q;
                }
            }
        __syncthreads();

        float mean[2][2], rstd[2][2];
#pragma unroll
        for (int i = 0; i < 2; i++)
#pragma unroll
            for (int h2 = 0; h2 < 2; h2++) {
                int row = wm * 32 + i * 16 + g + 8 * h2;
                float s = spart[row * 8 + 0] + spart[row * 8 + 2] +
                          spart[row * 8 + 4] + spart[row * 8 + 6];
                float q = spart[row * 8 + 1] + spart[row * 8 + 3] +
                          spart[row * 8 + 5] + spart[row * 8 + 7];
                float m = s * (1.0f / CDIM);
                mean[i][h2] = m;
                rstd[i][h2] = rsqrtf(q * (1.0f / CDIM) - m * m + 1e-5f);
            }

#pragma unroll
        for (int i = 0; i < 2; i++)
#pragma unroll
            for (int h2 = 0; h2 < 2; h2++) {
                int rr = m0 + wm * 32 + i * 16 + g + 8 * h2;
                size_t off = (LNF == 1) ? gather_off(rr) : (size_t)rr * CDIM;
                float m = mean[i][h2], rs = rstd[i][h2];
#pragma unroll
                for (int j = 0; j < 6; j++) {
                    int cc = wn * 48 + j * 8 + tg * 2;
                    float v0 = acc[i][j][h2 * 2 + 0];
                    float v1 = acc[i][j][h2 * 2 + 1];
                    float y0 = (v0 - m) * rs * lnw[cc]     + lnb[cc];
                    float y1 = (v1 - m) * rs * lnw[cc + 1] + lnb[cc + 1];
                    float2 rv = *(const float2*)(res + off + cc);
                    *(float2*)(out + off + cc) = make_float2(rv.x + y0, rv.y + y1);
                }
            }
    }
}

// ---------------- tensor-core attention (unchanged) ----------------
#define OQH 0
#define OQL 2304
#define OKH 4608
#define OKL 6912
#define OVT 9216
#define OP  11392
#define OQI 15744
#define OKI 15808
#define OTAB 15872
#define OGID 16048
#define ATT_SMEM_FLOATS 16112
#define ATT_SMEM_BYTES (ATT_SMEM_FLOATS * 4)

__global__ void __launch_bounds__(128) attn_kernel() {
    extern __shared__ float smx[];
    float* sQh = smx + OQH;
    float* sQl = smx + OQL;
    float* sKh = smx + OKH;
    float* sKl = smx + OKL;
    float* sVT = smx + OVT;
    float* sP  = smx + OP;
    float* qinv = smx + OQI;
    float* kinv = smx + OKI;
    float* stab = smx + OTAB;
    int*   sgid = (int*)(smx + OGID);

    int blk = blockIdx.x;
    int w = blk / NHEAD;
    int h = blk - w * NHEAD;
    int tid = threadIdx.x;
    int lane = tid & 31, wr = tid >> 5;
    int g = lane >> 2, tg = lane & 3;

    size_t base = ((size_t)(w * NHEAD + h) * NTOK) * HDIM;
    const float* qp = g_qkv + base;
    const float* kp = g_qkv + (size_t)QKVSZ + base;
    const float* vp = g_qkv + 2 * (size_t)QKVSZ + base;

    for (int i = tid; i < 15 * 32; i += 128) {
        int r = 49 + (i >> 5), c = i & 31;
        sQh[r * 36 + c] = 0.f; sQl[r * 36 + c] = 0.f;
        sKh[r * 36 + c] = 0.f; sKl[r * 36 + c] = 0.f;
    }
    for (int i = tid; i < 32 * 16; i += 128) {
        int d = i >> 4, j = 48 + (i & 15);
        sVT[d * 68 + j] = 0.f;
    }

    for (int idx = tid; idx < 392; idx += 128) {
        int r = idx >> 3, c4 = (idx & 7) * 4;
        float4 q = *(const float4*)(qp + r * 32 + c4);
        float4 k = *(const float4*)(kp + r * 32 + c4);
        float4 v = *(const float4*)(vp + r * 32 + c4);
        float qh0 = f2tff(q.x), qh1 = f2tff(q.y), qh2 = f2tff(q.z), qh3 = f2tff(q.w);
        sQh[r * 36 + c4 + 0] = qh0; sQl[r * 36 + c4 + 0] = f2tff(q.x - qh0);
        sQh[r * 36 + c4 + 1] = qh1; sQl[r * 36 + c4 + 1] = f2tff(q.y - qh1);
        sQh[r * 36 + c4 + 2] = qh2; sQl[r * 36 + c4 + 2] = f2tff(q.z - qh2);
        sQh[r * 36 + c4 + 3] = qh3; sQl[r * 36 + c4 + 3] = f2tff(q.w - qh3);
        float kh0 = f2tff(k.x), kh1 = f2tff(k.y), kh2 = f2tff(k.z), kh3 = f2tff(k.w);
        sKh[r * 36 + c4 + 0] = kh0; sKl[r * 36 + c4 + 0] = f2tff(k.x - kh0);
        sKh[r * 36 + c4 + 1] = kh1; sKl[r * 36 + c4 + 1] = f2tff(k.y - kh1);
        sKh[r * 36 + c4 + 2] = kh2; sKl[r * 36 + c4 + 2] = f2tff(k.z - kh2);
        sKh[r * 36 + c4 + 3] = kh3; sKl[r * 36 + c4 + 3] = f2tff(k.w - kh3);
        sVT[(c4 + 0) * 68 + r] = f2tff(v.x);
        sVT[(c4 + 1) * 68 + r] = f2tff(v.y);
        sVT[(c4 + 2) * 68 + r] = f2tff(v.z);
        sVT[(c4 + 3) * 68 + r] = f2tff(v.w);
    }
    for (int i = tid; i < 169; i += 128) stab[i] = g_tabsig[i * NHEAD + h];

    int win = w & 63;
    int wi = win >> 3, wj = win & 7;
    if (tid < 64) {
        int t = (tid < 49) ? tid : 48;
        int r = t / WSZ, c = t - r * WSZ;
        int sh = wi * WSZ + r, sw = wj * WSZ + c;
        int gh = (sh < 49) ? 0 : ((sh < 53) ? 1 : 2);
        int gw = (sw < 49) ? 0 : ((sw < 53) ? 1 : 2);
        sgid[tid] = gh * 3 + gw;
    }
    __syncthreads();

    if (tid < 49) {
        float s = 0.f;
#pragma unroll
        for (int d = 0; d < 32; d++) {
            float v = sQh[tid * 36 + d] + sQl[tid * 36 + d];
            s = fmaf(v, v, s);
        }
        qinv[tid] = 1.0f / fmaxf(sqrtf(s), 1e-12f);
    } else if (tid >= 64 && tid < 64 + 49) {
        int r = tid - 64;
        float s = 0.f;
#pragma unroll
        for (int d = 0; d < 32; d++) {
            float v = sKh[r * 36 + d] + sKl[r * 36 + d];
            s = fmaf(v, v, s);
        }
        kinv[r] = 1.0f / fmaxf(sqrtf(s), 1e-12f);
    }
    __syncthreads();

    float acc[8][4];
#pragma unroll
    for (int n = 0; n < 8; n++)
#pragma unroll
        for (int r = 0; r < 4; r++) acc[n][r] = 0.f;

    int arow = wr * 16 + g;
#pragma unroll
    for (int kk = 0; kk < 4; kk++) {
        int kb = kk * 8;
        unsigned ah[4], al[4];
        ah[0] = __float_as_uint(sQh[arow * 36 + kb + tg]);
        ah[1] = __float_as_uint(sQh[(arow + 8) * 36 + kb + tg]);
        ah[2] = __float_as_uint(sQh[arow * 36 + kb + tg + 4]);
        ah[3] = __float_as_uint(sQh[(arow + 8) * 36 + kb + tg + 4]);
        al[0] = __float_as_uint(sQl[arow * 36 + kb + tg]);
        al[1] = __float_as_uint(sQl[(arow + 8) * 36 + kb + tg]);
        al[2] = __float_as_uint(sQl[arow * 36 + kb + tg + 4]);
        al[3] = __float_as_uint(sQl[(arow + 8) * 36 + kb + tg + 4]);
#pragma unroll
        for (int n = 0; n < 8; n++) {
            int bj = n * 8 + g;
            unsigned bh[2], bl[2];
            bh[0] = __float_as_uint(sKh[bj * 36 + kb + tg]);
            bh[1] = __float_as_uint(sKh[bj * 36 + kb + tg + 4]);
            bl[0] = __float_as_uint(sKl[bj * 36 + kb + tg]);
            bl[1] = __float_as_uint(sKl[bj * 36 + kb + tg + 4]);
            mma_tf32(acc[n], al, bh);
            mma_tf32(acc[n], ah, bl);
            mma_tf32(acc[n], ah, bh);
        }
    }

    float scale = g_scale[h];
    int iA = wr * 16 + g, iB = iA + 8;
    bool vA = (iA < 49), vB = (iB < 49);
    int riA = 0, ciA = 0, giA = 0, riB = 0, ciB = 0, giB = 0;
    float qsA = 0.f, qsB = 0.f;
    if (vA) { riA = iA / WSZ; ciA = iA - riA * WSZ; giA = sgid[iA]; qsA = qinv[iA] * scale; }
    if (vB) { riB = iB / WSZ; ciB = iB - riB * WSZ; giB = sgid[iB]; qsB = qinv[iB] * scale; }

#pragma unroll
    for (int n = 0; n < 8; n++) {
#pragma unroll
        for (int r = 0; r < 4; r++) {
            int j = n * 8 + tg * 2 + (r & 1);
            bool top = (r < 2);
            bool vi = top ? vA : vB;
            float L = -1e30f;
            if (vi && j < 49) {
                int rj = j / WSZ, cj = j - rj * WSZ;
                int ri = top ? riA : riB, ci = top ? ciA : ciB;
                int gi = top ? giA : giB;
                float qs = top ? qsA : qsB;
                int idx = (ri - rj + 6) * 13 + (ci - cj + 6);
                float mval = (gi != sgid[j]) ? -100.f : 0.f;
                L = acc[n][r] * qs * kinv[j] + stab[idx] + mval;
            }
            acc[n][r] = L;
        }
    }

    float mA = -1e30f, mB = -1e30f;
#pragma unroll
    for (int n = 0; n < 8; n++) {
        mA = fmaxf(mA, fmaxf(acc[n][0], acc[n][1]));
        mB = fmaxf(mB, fmaxf(acc[n][2], acc[n][3]));
    }
    mA = fmaxf(mA, __shfl_xor_sync(0xffffffffu, mA, 1));
    mA = fmaxf(mA, __shfl_xor_sync(0xffffffffu, mA, 2));
    mB = fmaxf(mB, __shfl_xor_sync(0xffffffffu, mB, 1));
    mB = fmaxf(mB, __shfl_xor_sync(0xffffffffu, mB, 2));

    float sA = 0.f, sB = 0.f;
#pragma unroll
    for (int n = 0; n < 8; n++) {
        float e0 = __expf(acc[n][0] - mA); acc[n][0] = e0; sA += e0;
        float e1 = __expf(acc[n][1] - mA); acc[n][1] = e1; sA += e1;
        float e2 = __expf(acc[n][2] - mB); acc[n][2] = e2; sB += e2;
        float e3 = __expf(acc[n][3] - mB); acc[n][3] = e3; sB += e3;
    }
    sA += __shfl_xor_sync(0xffffffffu, sA, 1);
    sA += __shfl_xor_sync(0xffffffffu, sA, 2);
    sB += __shfl_xor_sync(0xffffffffu, sB, 1);
    sB += __shfl_xor_sync(0xffffffffu, sB, 2);
    float rA = 1.0f / sA, rB = 1.0f / sB;

#pragma unroll
    for (int n = 0; n < 8; n++) {
        int jc = n * 8 + tg * 2;
        sP[iA * 68 + jc]     = f2tff(acc[n][0] * rA);
        sP[iA * 68 + jc + 1] = f2tff(acc[n][1] * rA);
        sP[iB * 68 + jc]     = f2tff(acc[n][2] * rB);
        sP[iB * 68 + jc + 1] = f2tff(acc[n][3] * rB);
    }
    __syncthreads();

    float o[4][4];
#pragma unroll
    for (int nt = 0; nt < 4; nt++)
#pragma unroll
        for (int r = 0; r < 4; r++) o[nt][r] = 0.f;

#pragma unroll
    for (int kk = 0; kk < 8; kk++) {
        int kb = kk * 8;
        unsigned a[4];
        a[0] = __float_as_uint(sP[iA * 68 + kb + tg]);
        a[1] = __float_as_uint(sP[iB * 68 + kb + tg]);
        a[2] = __float_as_uint(sP[iA * 68 + kb + tg + 4]);
        a[3] = __float_as_uint(sP[iB * 68 + kb + tg + 4]);
#pragma unroll
        for (int nt = 0; nt < 4; nt++) {
            unsigned b[2];
            b[0] = __float_as_uint(sVT[(nt * 8 + g) * 68 + kb + tg]);
            b[1] = __float_as_uint(sVT[(nt * 8 + g) * 68 + kb + tg + 4]);
            mma_tf32(o[nt], a, b);
        }
    }

    if (vA) {
        size_t ob = ((size_t)(w * NTOK + iA)) * CDIM + h * HDIM;
#pragma unroll
        for (int nt = 0; nt < 4; nt++)
            *(float2*)&g_attnout[ob + nt * 8 + tg * 2] = make_float2(o[nt][0], o[nt][1]);
    }
    if (vB) {
        size_t ob = ((size_t)(w * NTOK + iB)) * CDIM + h * HDIM;
#pragma unroll
        for (int nt = 0; nt < 4; nt++)
            *(float2*)&g_attnout[ob + nt * 8 + tg * 2] = make_float2(o[nt][2], o[nt][3]);
    }
}

// ---------------- launcher ----------------
extern "C" void kernel_launch(void* const* d_in, const int* in_sizes, int n_in,
                              void* d_out, int out_size) {
    const float* x       = (const float*)d_in[0];
    const float* qkv_w   = (const float*)d_in[1];
    const float* qkv_b   = (const float*)d_in[2];
    const float* proj_w  = (const float*)d_in[3];
    const float* proj_b  = (const float*)d_in[4];
    const float* lscale  = (const float*)d_in[5];
    const float* cpb_w1  = (const float*)d_in[6];
    const float* cpb_b1  = (const float*)d_in[7];
    const float* cpb_w2  = (const float*)d_in[8];
    const float* n1w     = (const float*)d_in[9];
    const float* n1b     = (const float*)d_in[10];
    const float* n2w     = (const float*)d_in[11];
    const float* n2b     = (const float*)d_in[12];
    const float* fc1_w   = (const float*)d_in[13];
    const float* fc1_b   = (const float*)d_in[14];
    const float* fc2_w   = (const float*)d_in[15];
    const float* fc2_b   = (const float*)d_in[16];
    float* out = (float*)d_out;

    float *p_attn, *p_x1, *p_hid;
    cudaGetSymbolAddress((void**)&p_attn, g_attnout);
    cudaGetSymbolAddress((void**)&p_x1,   g_x1);
    cudaGetSymbolAddress((void**)&p_hid,  g_hidden);

    cudaFuncSetAttribute(attn_kernel,
        cudaFuncAttributeMaxDynamicSharedMemorySize, ATT_SMEM_BYTES);

    const int MT = TOK / 64;  // 1568

    tab_kernel<<<1, 256>>>(cpb_w1, cpb_b1, cpb_w2, lscale);
    // QKV: gather A from x, scatter epilogue to g_qkv. N=576 -> 3 tiles of 192
    tgemm_kernel<1, 0, 1, 0><<<dim3(3, MT), 256>>>(
        x, qkv_w, qkv_b, nullptr, nullptr, nullptr, nullptr, CDIM, 576);
    attn_kernel<<<BWIN * NHEAD, 128, ATT_SMEM_BYTES>>>();
    // proj + LN1 + residual(x, gathered) -> x1
    tgemm_kernel<0, 0, 0, 1><<<dim3(1, MT), 256>>>(
        p_attn, proj_w, proj_b, p_x1, n1w, n1b, x, CDIM, CDIM);
    // fc1 + GELU -> hidden. N=768 -> 4 tiles of 192
    tgemm_kernel<0, 1, 0, 0><<<dim3(4, MT), 256>>>(
        p_x1, fc1_w, fc1_b, p_hid, nullptr, nullptr, nullptr, CDIM, MLPH);
    // fc2 + LN2 + residual(x1) -> out
    tgemm_kernel<0, 0, 0, 2><<<dim3(1, MT), 256>>>(
        p_hid, fc2_w, fc2_b, out, n2w, n2b, p_x1, MLPH, CDIM);
}

// round 17
// speedup vs baseline: 3.9202x; 1.2351x over previous
#include <cuda_runtime.h>
#include <cuda_fp16.h>
#include <cuda_bf16.h>
#include <math.h>

// ---------------- problem constants ----------------
#define BATCH 32
#define IMG   56
#define CDIM  192
#define NHEAD 6
#define HDIM  32
#define WSZ   7
#define NTOK  49
#define NWIN  64
#define BWIN  (BATCH*NWIN)  // 2048
#define TOK   (BWIN*NTOK)   // 100352
#define MLPH  768

#define QKVSZ (BWIN*NHEAD*NTOK*HDIM)

// ---------------- scratch ----------------
__device__ float g_qkv[3u * (size_t)QKVSZ];
__device__ float g_attnout[(size_t)TOK * CDIM];
__device__ float g_x1[(size_t)BATCH * IMG * IMG * CDIM];
__device__ float g_hidden[(size_t)TOK * MLPH];
__device__ float g_tabsig[169 * NHEAD];
__device__ float g_scale[NHEAD];

// ---------------- CPB table + scale (tiny) ----------------
__global__ void tab_kernel(const float* __restrict__ w1, const float* __restrict__ b1,
                           const float* __restrict__ w2, const float* __restrict__ ls) {
    __shared__ float sW1[1024];
    __shared__ float sB1[512];
    __shared__ float sW2[NHEAD * 512];
    int tid = threadIdx.x;
    for (int i = tid; i < 1024; i += blockDim.x) sW1[i] = w1[i];
    for (int i = tid; i < 512;  i += blockDim.x) sB1[i] = b1[i];
    for (int i = tid; i < NHEAD * 512; i += blockDim.x) sW2[i] = w2[i];
    __syncthreads();

    if (tid < 169) {
        int i = tid / 13, j = tid % 13;
        float vh = (float)(i - 6) * (7.0f / 6.0f);
        float vw = (float)(j - 6) * (7.0f / 6.0f);
        const float inv_log2_7 = 0.35620719f;
        float th = copysignf(log2f(fabsf(vh) + 1.0f) * inv_log2_7, vh);
        float tw = copysignf(log2f(fabsf(vw) + 1.0f) * inv_log2_7, vw);
        float acc[NHEAD];
#pragma unroll
        for (int h = 0; h < NHEAD; h++) acc[h] = 0.f;
        for (int jj = 0; jj < 512; jj++) {
            float hval = fmaf(th, sW1[2 * jj], fmaf(tw, sW1[2 * jj + 1], sB1[jj]));
            hval = (hval > 0.f) ? hval : 0.01f * hval;
#pragma unroll
            for (int h = 0; h < NHEAD; h++) acc[h] = fmaf(hval, sW2[h * 512 + jj], acc[h]);
        }
#pragma unroll
        for (int h = 0; h < NHEAD; h++)
            g_tabsig[tid * NHEAD + h] = 14.f / (1.f + expf(-acc[h]));
    }
    if (tid < NHEAD) g_scale[tid] = expf(fminf(ls[tid], logf(100.f)));
}

// ---------------- mma helpers ----------------
__device__ __forceinline__ unsigned f2tf(float f) {
    unsigned r; asm("cvt.rna.tf32.f32 %0, %1;" : "=r"(r) : "f"(f)); return r;
}
__device__ __forceinline__ float f2tff(float f) {
    return __uint_as_float(f2tf(f));
}
__device__ __forceinline__ void mma_tf32(float* c, const unsigned* a, const unsigned* b) {
    asm volatile("mma.sync.aligned.m16n8k8.row.col.f32.tf32.tf32.f32 "
        "{%0,%1,%2,%3}, {%4,%5,%6,%7}, {%8,%9}, {%0,%1,%2,%3};"
        : "+f"(c[0]), "+f"(c[1]), "+f"(c[2]), "+f"(c[3])
        : "r"(a[0]), "r"(a[1]), "r"(a[2]), "r"(a[3]), "r"(b[0]), "r"(b[1]));
}
__device__ __forceinline__ void mma_f16(float* c, const unsigned* a, const unsigned* b) {
    asm volatile("mma.sync.aligned.m16n8k16.row.col.f32.f16.f16.f32 "
        "{%0,%1,%2,%3}, {%4,%5,%6,%7}, {%8,%9}, {%0,%1,%2,%3};"
        : "+f"(c[0]), "+f"(c[1]), "+f"(c[2]), "+f"(c[3])
        : "r"(a[0]), "r"(a[1]), "r"(a[2]), "r"(a[3]), "r"(b[0]), "r"(b[1]));
}
__device__ __forceinline__ unsigned f2h2u(float lo, float hi) {
    __half2 h = __floats2half2_rn(lo, hi);
    return *(unsigned*)&h;
}

__device__ __forceinline__ size_t gather_off(int m) {
    int wv = m / NTOK, tk = m - wv * NTOK;
    int bb = wv >> 6, win = wv & 63;
    int r = tk / WSZ, c = tk - r * WSZ;
    int hp = (win >> 3) * WSZ + r + 3; if (hp >= IMG) hp -= IMG;
    int wp = (win & 7) * WSZ + c + 3;  if (wp >= IMG) wp -= IMG;
    return ((size_t)((bb * IMG + hp) * IMG + wp)) * CDIM;
}

// ---------------- fp16 GEMM: block 64x192, 8 warps of 32x48 ----------------
// Each smem row = 16 k-halves packed as 8 uints + 4 pad -> pitch 12 uints (48B).
// Fragment LDS pattern (12*g + tg mod 32) is a permutation -> conflict-free.
#define UPITCH 12

template <int GATHER, int ACT, int SCATTER, int LNF>
__global__ void __launch_bounds__(256, 2) tgemm_kernel(
        const float* __restrict__ A, const float* __restrict__ Wg,
        const float* __restrict__ bias, float* __restrict__ out,
        const float* __restrict__ lnw, const float* __restrict__ lnb,
        const float* __restrict__ res,
        int K, int Ndim) {
    __shared__ __align__(16) unsigned As[2][64 * UPITCH];
    __shared__ __align__(16) unsigned Bs[2][192 * UPITCH];
    int tid = threadIdx.x;
    int m0 = blockIdx.y * 64, n0 = blockIdx.x * 192;

    // A: 64 rows x 4 segs = 256 tasks, 1/thread. seg = 4 floats -> 2 uints.
    int arow_ = tid >> 2;
    int aseg = tid & 3;
    int aoff = arow_ * UPITCH + aseg * 2;
    const float* arowp = GATHER ? (A + gather_off(m0 + arow_))
                                : (A + (size_t)(m0 + arow_) * K);
    // B: 192 rows x 4 segs = 768 tasks, 3/thread
    const float* browp[3];
    int boff[3], bseg[3];
#pragma unroll
    for (int s = 0; s < 3; s++) {
        int v = tid + s * 256;
        int row = v >> 2;
        bseg[s] = v & 3;
        boff[s] = row * UPITCH + bseg[s] * 2;
        browp[s] = Wg + (size_t)(n0 + row) * K;
    }

    int lane = tid & 31, w = tid >> 5;
    int wm = w & 1, wn = w >> 1;          // 2(M) x 4(N), warp tile 32x48
    int g = lane >> 2, tg = lane & 3;

    float acc[2][6][4];
#pragma unroll
    for (int i = 0; i < 2; i++)
#pragma unroll
        for (int j = 0; j < 6; j++)
#pragma unroll
            for (int r = 0; r < 4; r++) acc[i][j][r] = 0.f;

    float4 pa, pb[3];
    pa = *(const float4*)(arowp + aseg * 4);
#pragma unroll
    for (int s = 0; s < 3; s++) pb[s] = *(const float4*)(browp[s] + bseg[s] * 4);

    int buf = 0;
    for (int k0 = 0; k0 < K; k0 += 16) {
        *(uint2*)&As[buf][aoff] = make_uint2(f2h2u(pa.x, pa.y), f2h2u(pa.z, pa.w));
#pragma unroll
        for (int s = 0; s < 3; s++)
            *(uint2*)&Bs[buf][boff[s]] = make_uint2(f2h2u(pb[s].x, pb[s].y), f2h2u(pb[s].z, pb[s].w));
        __syncthreads();

        int kn = k0 + 16;
        if (kn < K) {
            pa = *(const float4*)(arowp + kn + aseg * 4);
#pragma unroll
            for (int s = 0; s < 3; s++) pb[s] = *(const float4*)(browp[s] + kn + bseg[s] * 4);
        }

        // fragment loads: same index pattern as proven tf32 version, uint granularity
        unsigned a[2][4], b[6][2];
#pragma unroll
        for (int i = 0; i < 2; i++) {
            int mr = wm * 32 + i * 16 + g;
            a[i][0] = As[buf][mr * UPITCH + tg];
            a[i][1] = As[buf][(mr + 8) * UPITCH + tg];
            a[i][2] = As[buf][mr * UPITCH + 4 + tg];
            a[i][3] = As[buf][(mr + 8) * UPITCH + 4 + tg];
        }
#pragma unroll
        for (int j = 0; j < 6; j++) {
            int nc = wn * 48 + j * 8 + g;
            b[j][0] = Bs[buf][nc * UPITCH + tg];
            b[j][1] = Bs[buf][nc * UPITCH + 4 + tg];
        }
#pragma unroll
        for (int i = 0; i < 2; i++)
#pragma unroll
            for (int j = 0; j < 6; j++)
                mma_f16(acc[i][j], a[i], b[j]);
        buf ^= 1;
    }

    if (LNF == 0) {
#pragma unroll
        for (int i = 0; i < 2; i++) {
            int rowb = m0 + wm * 32 + i * 16 + g;
#pragma unroll
            for (int j = 0; j < 6; j++) {
                int colb = n0 + wn * 48 + j * 8 + tg * 2;
#pragma unroll
                for (int r = 0; r < 4; r++) {
                    int rr = rowb + (r >> 1) * 8;
                    int cc = colb + (r & 1);
                    float v = acc[i][j][r] + bias[cc];
                    if (ACT == 1) v = 0.5f * v * (1.0f + erff(v * 0.70710678118654752f));
                    if (SCATTER) {
                        int which = cc / CDIM;
                        int rem = cc - which * CDIM;
                        int head = rem >> 5, dd = rem & 31;
                        int wv = rr / NTOK, tk = rr - wv * NTOK;
                        g_qkv[(size_t)which * QKVSZ +
                              ((size_t)(wv * NHEAD + head) * NTOK + tk) * HDIM + dd] = v;
                    } else {
                        out[(size_t)rr * Ndim + cc] = v;
                    }
                }
            }
        }
    } else {
        // fused LayerNorm + residual epilogue (N tile == full C == 192, n0 == 0)
        __syncthreads();
        float* spart = (float*)As;             // [64 rows][4 wn][sum,sq] = 512 floats

        float vsum[2][2], vsq[2][2];
#pragma unroll
        for (int i = 0; i < 2; i++) { vsum[i][0] = vsum[i][1] = 0.f; vsq[i][0] = vsq[i][1] = 0.f; }
#pragma unroll
        for (int i = 0; i < 2; i++)
#pragma unroll
            for (int j = 0; j < 6; j++)
#pragma unroll
                for (int r = 0; r < 4; r++) {
                    int cc = wn * 48 + j * 8 + tg * 2 + (r & 1);
                    float v = acc[i][j][r] + bias[cc];
                    acc[i][j][r] = v;
                    vsum[i][r >> 1] += v;
                    vsq[i][r >> 1] = fmaf(v, v, vsq[i][r >> 1]);
                }
#pragma unroll
        for (int i = 0; i < 2; i++)
#pragma unroll
            for (int h2 = 0; h2 < 2; h2++) {
                float s = vsum[i][h2], q = vsq[i][h2];
                s += __shfl_xor_sync(0xffffffffu, s, 1);
                s += __shfl_xor_sync(0xffffffffu, s, 2);
                q += __shfl_xor_sync(0xffffffffu, q, 1);
                q += __shfl_xor_sync(0xffffffffu, q, 2);
                if (tg == 0) {
                    int row = wm * 32 + i * 16 + g + 8 * h2;
                    spart[row * 8 + wn * 2]     = s;
                    spart[row * 8 + wn * 2 + 1] = q;
                }
            }
        __syncthreads();

        float mean[2][2], rstd[2][2];
#pragma unroll
        for (int i = 0; i < 2; i++)
#pragma unroll
            for (int h2 = 0; h2 < 2; h2++) {
                int row = wm * 32 + i * 16 + g + 8 * h2;
                float s = spart[row * 8 + 0] + spart[row * 8 + 2] +
                          spart[row * 8 + 4] + spart[row * 8 + 6];
                float q = spart[row * 8 + 1] + spart[row * 8 + 3] +
                          spart[row * 8 + 5] + spart[row * 8 + 7];
                float m = s * (1.0f / CDIM);
                mean[i][h2] = m;
                rstd[i][h2] = rsqrtf(q * (1.0f / CDIM) - m * m + 1e-5f);
            }

#pragma unroll
        for (int i = 0; i < 2; i++)
#pragma unroll
            for (int h2 = 0; h2 < 2; h2++) {
                int rr = m0 + wm * 32 + i * 16 + g + 8 * h2;
                size_t off = (LNF == 1) ? gather_off(rr) : (size_t)rr * CDIM;
                float m = mean[i][h2], rs = rstd[i][h2];
#pragma unroll
                for (int j = 0; j < 6; j++) {
                    int cc = wn * 48 + j * 8 + tg * 2;
                    float v0 = acc[i][j][h2 * 2 + 0];
                    float v1 = acc[i][j][h2 * 2 + 1];
                    float y0 = (v0 - m) * rs * lnw[cc]     + lnb[cc];
                    float y1 = (v1 - m) * rs * lnw[cc + 1] + lnb[cc + 1];
                    float2 rv = *(const float2*)(res + off + cc);
                    *(float2*)(out + off + cc) = make_float2(rv.x + y0, rv.y + y1);
                }
            }
    }
}

// ---------------- tensor-core attention (unchanged, proven) ----------------
#define OQH 0
#define OQL 2304
#define OKH 4608
#define OKL 6912
#define OVT 9216
#define OP  11392
#define OQI 15744
#define OKI 15808
#define OTAB 15872
#define OGID 16048
#define ATT_SMEM_FLOATS 16112
#define ATT_SMEM_BYTES (ATT_SMEM_FLOATS * 4)

__global__ void __launch_bounds__(128) attn_kernel() {
    extern __shared__ float smx[];
    float* sQh = smx + OQH;
    float* sQl = smx + OQL;
    float* sKh = smx + OKH;
    float* sKl = smx + OKL;
    float* sVT = smx + OVT;
    float* sP  = smx + OP;
    float* qinv = smx + OQI;
    float* kinv = smx + OKI;
    float* stab = smx + OTAB;
    int*   sgid = (int*)(smx + OGID);

    int blk = blockIdx.x;
    int w = blk / NHEAD;
    int h = blk - w * NHEAD;
    int tid = threadIdx.x;
    int lane = tid & 31, wr = tid >> 5;
    int g = lane >> 2, tg = lane & 3;

    size_t base = ((size_t)(w * NHEAD + h) * NTOK) * HDIM;
    const float* qp = g_qkv + base;
    const float* kp = g_qkv + (size_t)QKVSZ + base;
    const float* vp = g_qkv + 2 * (size_t)QKVSZ + base;

    for (int i = tid; i < 15 * 32; i += 128) {
        int r = 49 + (i >> 5), c = i & 31;
        sQh[r * 36 + c] = 0.f; sQl[r * 36 + c] = 0.f;
        sKh[r * 36 + c] = 0.f; sKl[r * 36 + c] = 0.f;
    }
    for (int i = tid; i < 32 * 16; i += 128) {
        int d = i >> 4, j = 48 + (i & 15);
        sVT[d * 68 + j] = 0.f;
    }

    for (int idx = tid; idx < 392; idx += 128) {
        int r = idx >> 3, c4 = (idx & 7) * 4;
        float4 q = *(const float4*)(qp + r * 32 + c4);
        float4 k = *(const float4*)(kp + r * 32 + c4);
        float4 v = *(const float4*)(vp + r * 32 + c4);
        float qh0 = f2tff(q.x), qh1 = f2tff(q.y), qh2 = f2tff(q.z), qh3 = f2tff(q.w);
        sQh[r * 36 + c4 + 0] = qh0; sQl[r * 36 + c4 + 0] = f2tff(q.x - qh0);
        sQh[r * 36 + c4 + 1] = qh1; sQl[r * 36 + c4 + 1] = f2tff(q.y - qh1);
        sQh[r * 36 + c4 + 2] = qh2; sQl[r * 36 + c4 + 2] = f2tff(q.z - qh2);
        sQh[r * 36 + c4 + 3] = qh3; sQl[r * 36 + c4 + 3] = f2tff(q.w - qh3);
        float kh0 = f2tff(k.x), kh1 = f2tff(k.y), kh2 = f2tff(k.z), kh3 = f2tff(k.w);
        sKh[r * 36 + c4 + 0] = kh0; sKl[r * 36 + c4 + 0] = f2tff(k.x - kh0);
        sKh[r * 36 + c4 + 1] = kh1; sKl[r * 36 + c4 + 1] = f2tff(k.y - kh1);
        sKh[r * 36 + c4 + 2] = kh2; sKl[r * 36 + c4 + 2] = f2tff(k.z - kh2);
        sKh[r * 36 + c4 + 3] = kh3; sKl[r * 36 + c4 + 3] = f2tff(k.w - kh3);
        sVT[(c4 + 0) * 68 + r] = f2tff(v.x);
        sVT[(c4 + 1) * 68 + r] = f2tff(v.y);
        sVT[(c4 + 2) * 68 + r] = f2tff(v.z);
        sVT[(c4 + 3) * 68 + r] = f2tff(v.w);
    }
    for (int i = tid; i < 169; i += 128) stab[i] = g_tabsig[i * NHEAD + h];

    int win = w & 63;
    int wi = win >> 3, wj = win & 7;
    if (tid < 64) {
        int t = (tid < 49) ? tid : 48;
        int r = t / WSZ, c = t - r * WSZ;
        int sh = wi * WSZ + r, sw = wj * WSZ + c;
        int gh = (sh < 49) ? 0 : ((sh < 53) ? 1 : 2);
        int gw = (sw < 49) ? 0 : ((sw < 53) ? 1 : 2);
        sgid[tid] = gh * 3 + gw;
    }
    __syncthreads();

    if (tid < 49) {
        float s = 0.f;
#pragma unroll
        for (int d = 0; d < 32; d++) {
            float v = sQh[tid * 36 + d] + sQl[tid * 36 + d];
            s = fmaf(v, v, s);
        }
        qinv[tid] = 1.0f / fmaxf(sqrtf(s), 1e-12f);
    } else if (tid >= 64 && tid < 64 + 49) {
        int r = tid - 64;
        float s = 0.f;
#pragma unroll
        for (int d = 0; d < 32; d++) {
            float v = sKh[r * 36 + d] + sKl[r * 36 + d];
            s = fmaf(v, v, s);
        }
        kinv[r] = 1.0f / fmaxf(sqrtf(s), 1e-12f);
    }
    __syncthreads();

    float acc[8][4];
#pragma unroll
    for (int n = 0; n < 8; n++)
#pragma unroll
        for (int r = 0; r < 4; r++) acc[n][r] = 0.f;

    int arow = wr * 16 + g;
#pragma unroll
    for (int kk = 0; kk < 4; kk++) {
        int kb = kk * 8;
        unsigned ah[4], al[4];
        ah[0] = __float_as_uint(sQh[arow * 36 + kb + tg]);
        ah[1] = __float_as_uint(sQh[(arow + 8) * 36 + kb + tg]);
        ah[2] = __float_as_uint(sQh[arow * 36 + kb + tg + 4]);
        ah[3] = __float_as_uint(sQh[(arow + 8) * 36 + kb + tg + 4]);
        al[0] = __float_as_uint(sQl[arow * 36 + kb + tg]);
        al[1] = __float_as_uint(sQl[(arow + 8) * 36 + kb + tg]);
        al[2] = __float_as_uint(sQl[arow * 36 + kb + tg + 4]);
        al[3] = __float_as_uint(sQl[(arow + 8) * 36 + kb + tg + 4]);
#pragma unroll
        for (int n = 0; n < 8; n++) {
            int bj = n * 8 + g;
            unsigned bh[2], bl[2];
            bh[0] = __float_as_uint(sKh[bj * 36 + kb + tg]);
            bh[1] = __float_as_uint(sKh[bj * 36 + kb + tg + 4]);
            bl[0] = __float_as_uint(sKl[bj * 36 + kb + tg]);
            bl[1] = __float_as_uint(sKl[bj * 36 + kb + tg + 4]);
            mma_tf32(acc[n], al, bh);
            mma_tf32(acc[n], ah, bl);
            mma_tf32(acc[n], ah, bh);
        }
    }

    float scale = g_scale[h];
    int iA = wr * 16 + g, iB = iA + 8;
    bool vA = (iA < 49), vB = (iB < 49);
    int riA = 0, ciA = 0, giA = 0, riB = 0, ciB = 0, giB = 0;
    float qsA = 0.f, qsB = 0.f;
    if (vA) { riA = iA / WSZ; ciA = iA - riA * WSZ; giA = sgid[iA]; qsA = qinv[iA] * scale; }
    if (vB) { riB = iB / WSZ; ciB = iB - riB * WSZ; giB = sgid[iB]; qsB = qinv[iB] * scale; }

#pragma unroll
    for (int n = 0; n < 8; n++) {
#pragma unroll
        for (int r = 0; r < 4; r++) {
            int j = n * 8 + tg * 2 + (r & 1);
            bool top = (r < 2);
            bool vi = top ? vA : vB;
            float L = -1e30f;
            if (vi && j < 49) {
                int rj = j / WSZ, cj = j - rj * WSZ;
                int ri = top ? riA : riB, ci = top ? ciA : ciB;
                int gi = top ? giA : giB;
                float qs = top ? qsA : qsB;
                int idx = (ri - rj + 6) * 13 + (ci - cj + 6);
                float mval = (gi != sgid[j]) ? -100.f : 0.f;
                L = acc[n][r] * qs * kinv[j] + stab[idx] + mval;
            }
            acc[n][r] = L;
        }
    }

    float mA = -1e30f, mB = -1e30f;
#pragma unroll
    for (int n = 0; n < 8; n++) {
        mA = fmaxf(mA, fmaxf(acc[n][0], acc[n][1]));
        mB = fmaxf(mB, fmaxf(acc[n][2], acc[n][3]));
    }
    mA = fmaxf(mA, __shfl_xor_sync(0xffffffffu, mA, 1));
    mA = fmaxf(mA, __shfl_xor_sync(0xffffffffu, mA, 2));
    mB = fmaxf(mB, __shfl_xor_sync(0xffffffffu, mB, 1));
    mB = fmaxf(mB, __shfl_xor_sync(0xffffffffu, mB, 2));

    float sA = 0.f, sB = 0.f;
#pragma unroll
    for (int n = 0; n < 8; n++) {
        float e0 = __expf(acc[n][0] - mA); acc[n][0] = e0; sA += e0;
        float e1 = __expf(acc[n][1] - mA); acc[n][1] = e1; sA += e1;
        float e2 = __expf(acc[n][2] - mB); acc[n][2] = e2; sB += e2;
        float e3 = __expf(acc[n][3] - mB); acc[n][3] = e3; sB += e3;
    }
    sA += __shfl_xor_sync(0xffffffffu, sA, 1);
    sA += __shfl_xor_sync(0xffffffffu, sA, 2);
    sB += __shfl_xor_sync(0xffffffffu, sB, 1);
    sB += __shfl_xor_sync(0xffffffffu, sB, 2);
    float rA = 1.0f / sA, rB = 1.0f / sB;

#pragma unroll
    for (int n = 0; n < 8; n++) {
        int jc = n * 8 + tg * 2;
        sP[iA * 68 + jc]     = f2tff(acc[n][0] * rA);
        sP[iA * 68 + jc + 1] = f2tff(acc[n][1] * rA);
        sP[iB * 68 + jc]     = f2tff(acc[n][2] * rB);
        sP[iB * 68 + jc + 1] = f2tff(acc[n][3] * rB);
    }
    __syncthreads();

    float o[4][4];
#pragma unroll
    for (int nt = 0; nt < 4; nt++)
#pragma unroll
        for (int r = 0; r < 4; r++) o[nt][r] = 0.f;

#pragma unroll
    for (int kk = 0; kk < 8; kk++) {
        int kb = kk * 8;
        unsigned a[4];
        a[0] = __float_as_uint(sP[iA * 68 + kb + tg]);
        a[1] = __float_as_uint(sP[iB * 68 + kb + tg]);
        a[2] = __float_as_uint(sP[iA * 68 + kb + tg + 4]);
        a[3] = __float_as_uint(sP[iB * 68 + kb + tg + 4]);
#pragma unroll
        for (int nt = 0; nt < 4; nt++) {
            unsigned b[2];
            b[0] = __float_as_uint(sVT[(nt * 8 + g) * 68 + kb + tg]);
            b[1] = __float_as_uint(sVT[(nt * 8 + g) * 68 + kb + tg + 4]);
            mma_tf32(o[nt], a, b);
        }
    }

    if (vA) {
        size_t ob = ((size_t)(w * NTOK + iA)) * CDIM + h * HDIM;
#pragma unroll
        for (int nt = 0; nt < 4; nt++)
            *(float2*)&g_attnout[ob + nt * 8 + tg * 2] = make_float2(o[nt][0], o[nt][1]);
    }
    if (vB) {
        size_t ob = ((size_t)(w * NTOK + iB)) * CDIM + h * HDIM;
#pragma unroll
        for (int nt = 0; nt < 4; nt++)
            *(float2*)&g_attnout[ob + nt * 8 + tg * 2] = make_float2(o[nt][2], o[nt][3]);
    }
}

// ---------------- launcher ----------------
extern "C" void kernel_launch(void* const* d_in, const int* in_sizes, int n_in,
                              void* d_out, int out_size) {
    const float* x       = (const float*)d_in[0];
    const float* qkv_w   = (const float*)d_in[1];
    const float* qkv_b   = (const float*)d_in[2];
    const float* proj_w  = (const float*)d_in[3];
    const float* proj_b  = (const float*)d_in[4];
    const float* lscale  = (const float*)d_in[5];
    const float* cpb_w1  = (const float*)d_in[6];
    const float* cpb_b1  = (const float*)d_in[7];
    const float* cpb_w2  = (const float*)d_in[8];
    const float* n1w     = (const float*)d_in[9];
    const float* n1b     = (const float*)d_in[10];
    const float* n2w     = (const float*)d_in[11];
    const float* n2b     = (const float*)d_in[12];
    const float* fc1_w   = (const float*)d_in[13];
    const float* fc1_b   = (const float*)d_in[14];
    const float* fc2_w   = (const float*)d_in[15];
    const float* fc2_b   = (const float*)d_in[16];
    float* out = (float*)d_out;

    float *p_attn, *p_x1, *p_hid;
    cudaGetSymbolAddress((void**)&p_attn, g_attnout);
    cudaGetSymbolAddress((void**)&p_x1,   g_x1);
    cudaGetSymbolAddress((void**)&p_hid,  g_hidden);

    cudaFuncSetAttribute(attn_kernel,
        cudaFuncAttributeMaxDynamicSharedMemorySize, ATT_SMEM_BYTES);

    const int MT = TOK / 64;  // 1568

    tab_kernel<<<1, 256>>>(cpb_w1, cpb_b1, cpb_w2, lscale);
    // QKV: gather A from x, scatter epilogue to g_qkv. N=576 -> 3 tiles of 192
    tgemm_kernel<1, 0, 1, 0><<<dim3(3, MT), 256>>>(
        x, qkv_w, qkv_b, nullptr, nullptr, nullptr, nullptr, CDIM, 576);
    attn_kernel<<<BWIN * NHEAD, 128, ATT_SMEM_BYTES>>>();
    // proj + LN1 + residual(x, gathered) -> x1
    tgemm_kernel<0, 0, 0, 1><<<dim3(1, MT), 256>>>(
        p_attn, proj_w, proj_b, p_x1, n1w, n1b, x, CDIM, CDIM);
    // fc1 + GELU -> hidden. N=768 -> 4 tiles of 192
    tgemm_kernel<0, 1, 0, 0><<<dim3(4, MT), 256>>>(
        p_x1, fc1_w, fc1_b, p_hid, nullptr, nullptr, nullptr, CDIM, MLPH);
    // fc2 + LN2 + residual(x1) -> out
    tgemm_kernel<0, 0, 0, 2><<<dim3(1, MT), 256>>>(
        p_hid, fc2_w, fc2_b, out, n2w, n2b, p_x1, MLPH, CDIM);
}